// round 3
// baseline (speedup 1.0000x reference)
#include <cuda_runtime.h>

// ---------------- problem constants ----------------
#define Bb 16
#define Nn 128
#define Mm 1024
#define DNd 512
#define DEe 256
#define WNw 128
#define WEw 128
#define Pp 512
#define HIDc 256
#define LR_OUT 9
#define CR_OUT 6
#define MR_OUT 17

// ---------------- scratch layout (floats) ----------------
#define OFF_T1  0LL          // (B,N,WN)      262144
#define OFF_H   262144LL     // (B,N,WN)      262144
#define OFF_EG  524288LL     // (B,M,DE)      4194304
#define OFF_T2  4718592LL    // (B,M,WE)      2097152
#define OFF_G   6815744LL    // (B,M,WE)      2097152
#define OFF_AGG 8912896LL    // (B,N,WE)      262144
#define OFF_XP  9175040LL    // (B,N,WN)      262144
#define OFF_EFP 9437184LL    // (B,P,DE)      2097152
#define OFF_QP  11534336LL   // (B,P,WE)      1048576
#define OFF_CI  12582912LL   // (B,P,512)     4194304
#define OFF_HID 16777216LL   // (B,P,HID)     2097152
#define SCRATCH_TOTAL 18874368LL

__device__ float g_scratch[SCRATCH_TOTAL];

// ---------------- generic tiled SGEMM ----------------
// C[b] = act( A[b] @ B[b] + bias ), row-major everywhere.
// Acnt: optional per-batch row count; A rows >= Acnt[b] treated as zero.
#define BM 64
#define BN 64
#define BK 16

__global__ __launch_bounds__(256)
void sgemm_kernel(const float* __restrict__ A, const float* __restrict__ Bm,
                  const float* __restrict__ bias, float* __restrict__ C,
                  int K, int Ncols,
                  long long sA, long long sB, long long sC,
                  const int* __restrict__ Acnt, int relu)
{
    const int bz = blockIdx.z;
    const float* Ab = A + (long long)bz * sA;
    const float* Bbp = Bm + (long long)bz * sB;
    float* Cb = C + (long long)bz * sC;
    const int tile_m = blockIdx.y * BM;
    const int tile_n = blockIdx.x * BN;
    const int tid = threadIdx.x;
    const int tx = tid & 15, ty = tid >> 4;

    __shared__ float As[BK][BM];
    __shared__ float Bs[BK][BN];

    const int rowlim = Acnt ? Acnt[bz] : 0x40000000;

    float acc[4][4];
#pragma unroll
    for (int i = 0; i < 4; i++)
#pragma unroll
        for (int j = 0; j < 4; j++) acc[i][j] = 0.f;

    for (int k0 = 0; k0 < K; k0 += BK) {
        {   // A tile: 64x16 = 256 float4, one per thread, stored transposed
            int r = tid >> 2;
            int c4 = (tid & 3) * 4;
            int grow = tile_m + r;
            float4 v;
            if (grow < rowlim) v = *(const float4*)&Ab[(long long)grow * K + k0 + c4];
            else v = make_float4(0.f, 0.f, 0.f, 0.f);
            As[c4 + 0][r] = v.x; As[c4 + 1][r] = v.y;
            As[c4 + 2][r] = v.z; As[c4 + 3][r] = v.w;
        }
        {   // B tile: 16x64 = 256 float4
            int r = tid >> 4;
            int c4 = (tid & 15) * 4;
            float4 v = *(const float4*)&Bbp[(long long)(k0 + r) * Ncols + tile_n + c4];
            *(float4*)&Bs[r][c4] = v;
        }
        __syncthreads();
#pragma unroll
        for (int k = 0; k < BK; k++) {
            float a[4], bb[4];
#pragma unroll
            for (int i = 0; i < 4; i++) a[i] = As[k][ty * 4 + i];
#pragma unroll
            for (int j = 0; j < 4; j++) bb[j] = Bs[k][tx * 4 + j];
#pragma unroll
            for (int i = 0; i < 4; i++)
#pragma unroll
                for (int j = 0; j < 4; j++)
                    acc[i][j] = fmaf(a[i], bb[j], acc[i][j]);
        }
        __syncthreads();
    }
#pragma unroll
    for (int i = 0; i < 4; i++) {
        int row = tile_m + ty * 4 + i;
#pragma unroll
        for (int j = 0; j < 4; j++) {
            int col = tile_n + tx * 4 + j;
            float v = acc[i][j];
            if (bias) v += bias[col];
            if (relu) v = fmaxf(v, 0.f);
            Cb[(long long)row * Ncols + col] = v;
        }
    }
}

// ---------------- propagate: C = mask_rows( relu( (Adj + I) @ T ) ) ----------------
// Adj is (K x K) per batch, T is (K x Ncols) per batch with zeroed masked rows.
__global__ __launch_bounds__(256)
void prop_kernel(const float* __restrict__ Adj, const float* __restrict__ T,
                 float* __restrict__ C, int K, int Ncols,
                 long long sAdj, long long sT, long long sC,
                 const int* __restrict__ cnt)
{
    const int bz = blockIdx.z;
    const float* Ab = Adj + (long long)bz * sAdj;
    const float* Tb = T + (long long)bz * sT;
    float* Cb = C + (long long)bz * sC;
    const int tile_m = blockIdx.y * BM;
    const int tile_n = blockIdx.x * BN;
    const int tid = threadIdx.x;
    const int tx = tid & 15, ty = tid >> 4;

    __shared__ float As[BK][BM];
    __shared__ float Bs[BK][BN];

    const int lim = cnt[bz];

    float acc[4][4];
#pragma unroll
    for (int i = 0; i < 4; i++)
#pragma unroll
        for (int j = 0; j < 4; j++) acc[i][j] = 0.f;

    for (int k0 = 0; k0 < K; k0 += BK) {
        {
            int r = tid >> 2;
            int c4 = (tid & 3) * 4;
            int grow = tile_m + r;
            float4 v = *(const float4*)&Ab[(long long)grow * K + k0 + c4];
            float vv[4] = {v.x, v.y, v.z, v.w};
#pragma unroll
            for (int e = 0; e < 4; e++)
                if (grow == k0 + c4 + e) vv[e] += 1.f;   // + identity
            As[c4 + 0][r] = vv[0]; As[c4 + 1][r] = vv[1];
            As[c4 + 2][r] = vv[2]; As[c4 + 3][r] = vv[3];
        }
        {
            int r = tid >> 4;
            int c4 = (tid & 15) * 4;
            float4 v = *(const float4*)&Tb[(long long)(k0 + r) * Ncols + tile_n + c4];
            *(float4*)&Bs[r][c4] = v;
        }
        __syncthreads();
#pragma unroll
        for (int k = 0; k < BK; k++) {
            float a[4], bb[4];
#pragma unroll
            for (int i = 0; i < 4; i++) a[i] = As[k][ty * 4 + i];
#pragma unroll
            for (int j = 0; j < 4; j++) bb[j] = Bs[k][tx * 4 + j];
#pragma unroll
            for (int i = 0; i < 4; i++)
#pragma unroll
                for (int j = 0; j < 4; j++)
                    acc[i][j] = fmaf(a[i], bb[j], acc[i][j]);
        }
        __syncthreads();
    }
#pragma unroll
    for (int i = 0; i < 4; i++) {
        int row = tile_m + ty * 4 + i;
        float rm = (row < lim) ? 1.f : 0.f;
#pragma unroll
        for (int j = 0; j < 4; j++) {
            int col = tile_n + tx * 4 + j;
            Cb[(long long)row * Ncols + col] = fmaxf(acc[i][j], 0.f) * rm;
        }
    }
}

// ---------------- gathers ----------------
__global__ void gather_eg_kernel(const float* __restrict__ ef, const int* __restrict__ eidx,
                                 const int* __restrict__ num_edges, float* __restrict__ Eg)
{
    int t = blockIdx.x * blockDim.x + threadIdx.x;   // B*M*(DE/4) = 1048576
    int c4 = t & 63;
    int m = (t >> 6) & (Mm - 1);
    int b = t >> 16;
    float4 v = make_float4(0.f, 0.f, 0.f, 0.f);
    if (m < num_edges[b]) {
        int s = eidx[b * 2 * Mm + m];
        int d = eidx[b * 2 * Mm + Mm + m];
        v = ((const float4*)ef)[(((long long)b * Nn + s) * Nn + d) * 64 + c4];
    }
    ((float4*)Eg)[t] = v;
}

__global__ void gather_efp_kernel(const float* __restrict__ ef, const int* __restrict__ pairs,
                                  float* __restrict__ EfP)
{
    int t = blockIdx.x * blockDim.x + threadIdx.x;   // B*P*(DE/4) = 524288
    int c4 = t & 63;
    int p = (t >> 6) & (Pp - 1);
    int b = t >> 15;
    int n0 = pairs[((long long)b * Pp + p) * 2 + 0];
    int n1 = pairs[((long long)b * Pp + p) * 2 + 1];
    ((float4*)EfP)[t] = ((const float4*)ef)[(((long long)b * Nn + n0) * Nn + n1) * 64 + c4];
}

// ---------------- agg scatter ----------------
__global__ void zero_kernel(float* __restrict__ p, int n)
{
    int t = blockIdx.x * blockDim.x + threadIdx.x;
    if (t < n) p[t] = 0.f;
}

__global__ void scatter_agg_kernel(const float* __restrict__ g, const int* __restrict__ eidx,
                                   const int* __restrict__ num_edges, float* __restrict__ agg)
{
    int bm = blockIdx.x;                 // B*M blocks, 128 threads
    int b = bm >> 10;
    int m = bm & (Mm - 1);
    if (m >= num_edges[b]) return;
    int s = eidx[b * 2 * Mm + m];
    atomicAdd(&agg[((long long)b * Nn + s) * WEw + threadIdx.x],
              g[((long long)bm) * WEw + threadIdx.x]);
}

// ---------------- classifier input assembly ----------------
__global__ void ci_assemble_kernel(const float* __restrict__ h, const float* __restrict__ agg,
                                   const float* __restrict__ xp, const float* __restrict__ qp,
                                   const int* __restrict__ pairs, const int* __restrict__ num_obj,
                                   float* __restrict__ ci)
{
    int bp = blockIdx.x;                 // B*P blocks, 128 threads
    int b = bp >> 9;
    int t = threadIdx.x;
    int n0 = pairs[(long long)bp * 2 + 0];
    int n1 = pairs[(long long)bp * 2 + 1];
    int no = num_obj[b];

    const float* hb = h + (long long)b * Nn * WNw;
    const float* ab = agg + (long long)b * Nn * WEw;
    const float* xb = xp + (long long)b * Nn * WNw;

    float hv = hb[n0 * WNw + t] + hb[n1 * WNw + t];
    float av = (n0 < no ? ab[n0 * WEw + t] : 0.f) + (n1 < no ? ab[n1 * WEw + t] : 0.f);
    float pm = fmaxf(xb[n0 * WNw + t] + xb[n1 * WNw + t], 0.f);
    float qv = qp[(long long)bp * WEw + t];

    float* o = ci + (long long)bp * 512;
    o[t] = hv;
    o[128 + t] = av;
    o[256 + t] = pm;
    o[384 + t] = qv;
}

// ---------------- layer 2 (small N): one warp per row ----------------
__global__ void layer2_kernel(const float* __restrict__ hid, const float* __restrict__ W2,
                              const float* __restrict__ b2, float* __restrict__ out, int outn)
{
    int gw = (blockIdx.x * blockDim.x + threadIdx.x) >> 5;
    int lane = threadIdx.x & 31;
    if (gw >= Bb * Pp) return;
    const float* hr = hid + (long long)gw * HIDc;
    if (lane < outn) {
        float acc = b2[lane];
#pragma unroll 8
        for (int k = 0; k < HIDc; k++)
            acc = fmaf(hr[k], W2[k * outn + lane], acc);
        out[(long long)gw * outn + lane] = acc;
    }
}

// ---------------- launch ----------------
extern "C" void kernel_launch(void* const* d_in, const int* in_sizes, int n_in,
                              void* d_out, int out_size)
{
    const float* node_features = (const float*)d_in[0];
    const float* edge_features = (const float*)d_in[1];
    const float* adj           = (const float*)d_in[2];
    const float* ladj          = (const float*)d_in[3];
    const int*   edge_index    = (const int*)d_in[4];
    const int*   pairs         = (const int*)d_in[5];
    const int*   num_obj       = (const int*)d_in[6];
    const int*   num_edges     = (const int*)d_in[7];
    const float* Wn  = (const float*)d_in[8];
    const float* We  = (const float*)d_in[9];
    const float* Wn2 = (const float*)d_in[10];
    const float* We2 = (const float*)d_in[11];
    const float* scr_W1 = (const float*)d_in[12];
    const float* scr_b1 = (const float*)d_in[13];
    const float* scr_W2 = (const float*)d_in[14];
    const float* scr_b2 = (const float*)d_in[15];
    const float* lr_W1 = (const float*)d_in[16];
    const float* lr_b1 = (const float*)d_in[17];
    const float* lr_W2 = (const float*)d_in[18];
    const float* lr_b2 = (const float*)d_in[19];
    const float* mr_W1 = (const float*)d_in[20];
    const float* mr_b1 = (const float*)d_in[21];
    const float* mr_W2 = (const float*)d_in[22];
    const float* mr_b2 = (const float*)d_in[23];

    float* out = (float*)d_out;

    float* sc = nullptr;
    cudaGetSymbolAddress((void**)&sc, g_scratch);

    float* T1  = sc + OFF_T1;
    float* H   = sc + OFF_H;
    float* EG  = sc + OFF_EG;
    float* T2  = sc + OFF_T2;
    float* G   = sc + OFF_G;
    float* AGG = sc + OFF_AGG;
    float* XP  = sc + OFF_XP;
    float* EFP = sc + OFF_EFP;
    float* QP  = sc + OFF_QP;
    float* CI  = sc + OFF_CI;
    float* HID = sc + OFF_HID;

    // 1. Eg gather (masked)
    gather_eg_kernel<<<4096, 256>>>(edge_features, edge_index, num_edges, EG);

    // 2. T1 = Xmask @ Wn   (B batched, rows masked by num_obj)
    sgemm_kernel<<<dim3(WNw / BN, Nn / BM, Bb), 256>>>(
        node_features, Wn, nullptr, T1, DNd, WNw,
        (long long)Nn * DNd, 0, (long long)Nn * WNw, num_obj, 0);

    // 3. h = rowmask(relu((adj + I) @ T1))
    prop_kernel<<<dim3(WNw / BN, Nn / BM, Bb), 256>>>(
        adj, T1, H, Nn, WNw,
        (long long)Nn * Nn, (long long)Nn * WNw, (long long)Nn * WNw, num_obj);

    // 4. T2 = Eg @ We
    sgemm_kernel<<<dim3(WEw / BN, Mm / BM, Bb), 256>>>(
        EG, We, nullptr, T2, DEe, WEw,
        (long long)Mm * DEe, 0, (long long)Mm * WEw, nullptr, 0);

    // 5. g = rowmask(relu((ladj + I) @ T2))   -- heaviest GEMM
    prop_kernel<<<dim3(WEw / BN, Mm / BM, Bb), 256>>>(
        ladj, T2, G, Mm, WEw,
        (long long)Mm * Mm, (long long)Mm * WEw, (long long)Mm * WEw, num_edges);

    // 6. agg = scatter_add(g by src)
    zero_kernel<<<(Bb * Nn * WEw + 255) / 256, 256>>>(AGG, Bb * Nn * WEw);
    scatter_agg_kernel<<<Bb * Mm, WEw>>>(G, edge_index, num_edges, AGG);

    // 7. Xp = Xmask @ Wn2
    sgemm_kernel<<<dim3(WNw / BN, Nn / BM, Bb), 256>>>(
        node_features, Wn2, nullptr, XP, DNd, WNw,
        (long long)Nn * DNd, 0, (long long)Nn * WNw, num_obj, 0);

    // 8. gather edge features at object pairs; Q = relu(EfP @ We2)
    gather_efp_kernel<<<2048, 256>>>(edge_features, pairs, EFP);
    sgemm_kernel<<<dim3(WEw / BN, (Bb * Pp) / BM, 1), 256>>>(
        EFP, We2, nullptr, QP, DEe, WEw, 0, 0, 0, nullptr, 1);

    // 9. assemble classifier input ci (B*P, 512)
    ci_assemble_kernel<<<Bb * Pp, 128>>>(H, AGG, XP, QP, pairs, num_obj, CI);

    // 10. three MLP heads; outputs concatenated (lr, cr, mr)
    float* out_lr = out;
    float* out_cr = out + (long long)Bb * Pp * LR_OUT;
    float* out_mr = out_cr + (long long)Bb * Pp * CR_OUT;

    // lr head
    sgemm_kernel<<<dim3(HIDc / BN, (Bb * Pp) / BM, 1), 256>>>(
        CI, lr_W1, lr_b1, HID, 512, HIDc, 0, 0, 0, nullptr, 1);
    layer2_kernel<<<(Bb * Pp * 32 + 255) / 256, 256>>>(HID, lr_W2, lr_b2, out_lr, LR_OUT);

    // cr (scr) head
    sgemm_kernel<<<dim3(HIDc / BN, (Bb * Pp) / BM, 1), 256>>>(
        CI, scr_W1, scr_b1, HID, 512, HIDc, 0, 0, 0, nullptr, 1);
    layer2_kernel<<<(Bb * Pp * 32 + 255) / 256, 256>>>(HID, scr_W2, scr_b2, out_cr, CR_OUT);

    // mr head
    sgemm_kernel<<<dim3(HIDc / BN, (Bb * Pp) / BM, 1), 256>>>(
        CI, mr_W1, mr_b1, HID, 512, HIDc, 0, 0, 0, nullptr, 1);
    layer2_kernel<<<(Bb * Pp * 32 + 255) / 256, 256>>>(HID, mr_W2, mr_b2, out_mr, MR_OUT);
}

// round 4
// speedup vs baseline: 2.0835x; 2.0835x over previous
#include <cuda_runtime.h>
#include <cstdint>

// ---------------- problem constants ----------------
#define Bb 16
#define Nn 128
#define Mm 1024
#define DNd 512
#define DEe 256
#define WNw 128
#define WEw 128
#define Pp 512
#define HIDc 256
#define LR_OUT 9
#define CR_OUT 6
#define MR_OUT 17

// ---------------- scratch layout (floats) ----------------
#define OFF_T1XP 0LL          // (2048, 256)  T1 = cols 0:128, XP = cols 128:256
#define OFF_EG   524288LL     // (16384, 256)
#define OFF_T2   4718592LL    // (16384, 128)
#define OFF_H    6815744LL    // (2048, 128)
#define OFF_AGG  7077888LL    // (2048, 128)
#define OFF_EFP  7340032LL    // (8192, 256)
#define OFF_QP   9437184LL    // (8192, 128)
#define OFF_CI   10485760LL   // (8192, 512)
#define OFF_HID  14680064LL   // (8192, 768)
#define OFF_WNC  20971520LL   // (512, 256)
#define OFF_W1C  21102592LL   // (512, 768)
#define OFF_B1C  21495808LL   // (768)
#define SCRATCH_TOTAL 21496576LL

__device__ float g_scratch[SCRATCH_TOTAL];

// ---------------- tf32 helpers ----------------
__device__ __forceinline__ uint32_t f2tf32(float x) {
    uint32_t r;
    asm("cvt.rna.tf32.f32 %0, %1;" : "=r"(r) : "f"(x));
    return r;
}

__device__ __forceinline__ void mma_tf32(float c[4],
                                         uint32_t a0, uint32_t a1, uint32_t a2, uint32_t a3,
                                         uint32_t b0, uint32_t b1) {
    asm volatile(
        "mma.sync.aligned.m16n8k8.row.col.f32.tf32.tf32.f32 "
        "{%0,%1,%2,%3},{%4,%5,%6,%7},{%8,%9},{%0,%1,%2,%3};"
        : "+f"(c[0]), "+f"(c[1]), "+f"(c[2]), "+f"(c[3])
        : "r"(a0), "r"(a1), "r"(a2), "r"(a3), "r"(b0), "r"(b1));
}

// ---------------- generic tf32 tensor-core GEMM ----------------
// C[M,N] = act( A[M,K] @ B[K,N] + bias ), all row-major, single 2D GEMM.
// Optional row masking: row r of A is zero unless (r & ((1<<shift)-1)) < cnt[r>>shift].
// Tiles: BM=64, BN=64, BK=16. 128 threads = 4 warps in 2x2, each warp 32x32.
__global__ __launch_bounds__(128)
void gemm_tf32_kernel(const float* __restrict__ A, const float* __restrict__ Bm,
                      const float* __restrict__ bias, float* __restrict__ C,
                      int M, int N, int K,
                      const int* __restrict__ cnt, int shift, int relu)
{
    __shared__ __align__(16) float As[64][20];
    __shared__ __align__(16) float Bs[16][68];

    const int tile_m = blockIdx.y * 64;
    const int tile_n = blockIdx.x * 64;
    const int tid = threadIdx.x;
    const int warp = tid >> 5;
    const int lane = tid & 31;
    const int warp_m = (warp & 1) * 32;
    const int warp_n = (warp >> 1) * 32;

    // A-load role: thread -> (row, 8-col chunk)
    const int ar = tid >> 1;
    const int ac8 = (tid & 1) * 8;
    const int grow = tile_m + ar;
    bool aok = true;
    if (cnt) aok = (grow & ((1 << shift) - 1)) < cnt[grow >> shift];
    const float* ap = A + (long long)grow * K + ac8;

    // B-load role
    const int br = tid >> 3;
    const int bc8 = (tid & 7) * 8;
    const float* bp = Bm + (long long)br * N + tile_n + bc8;

    float acc[2][4][4];
#pragma unroll
    for (int mi = 0; mi < 2; mi++)
#pragma unroll
        for (int ni = 0; ni < 4; ni++)
#pragma unroll
            for (int q = 0; q < 4; q++) acc[mi][ni][q] = 0.f;

    for (int k0 = 0; k0 < K; k0 += 16) {
        float4 av1, av2;
        if (aok) {
            av1 = *(const float4*)(ap + k0);
            av2 = *(const float4*)(ap + k0 + 4);
        } else {
            av1 = make_float4(0.f, 0.f, 0.f, 0.f);
            av2 = av1;
        }
        *(float4*)&As[ar][ac8] = av1;
        *(float4*)&As[ar][ac8 + 4] = av2;

        float4 bv1 = *(const float4*)(bp + (long long)k0 * N);
        float4 bv2 = *(const float4*)(bp + (long long)k0 * N + 4);
        *(float4*)&Bs[br][bc8] = bv1;
        *(float4*)&Bs[br][bc8 + 4] = bv2;

        __syncthreads();

#pragma unroll
        for (int kk = 0; kk < 16; kk += 8) {
            uint32_t af[2][4];
#pragma unroll
            for (int mi = 0; mi < 2; mi++) {
                int r0 = warp_m + mi * 16 + (lane >> 2);
                int c0 = kk + (lane & 3);
                af[mi][0] = f2tf32(As[r0][c0]);
                af[mi][1] = f2tf32(As[r0 + 8][c0]);
                af[mi][2] = f2tf32(As[r0][c0 + 4]);
                af[mi][3] = f2tf32(As[r0 + 8][c0 + 4]);
            }
            uint32_t bf[4][2];
#pragma unroll
            for (int ni = 0; ni < 4; ni++) {
                int cc = warp_n + ni * 8 + (lane >> 2);
                int rr = kk + (lane & 3);
                bf[ni][0] = f2tf32(Bs[rr][cc]);
                bf[ni][1] = f2tf32(Bs[rr + 4][cc]);
            }
#pragma unroll
            for (int mi = 0; mi < 2; mi++)
#pragma unroll
                for (int ni = 0; ni < 4; ni++)
                    mma_tf32(acc[mi][ni], af[mi][0], af[mi][1], af[mi][2], af[mi][3],
                             bf[ni][0], bf[ni][1]);
        }
        __syncthreads();
    }

    // epilogue
#pragma unroll
    for (int mi = 0; mi < 2; mi++) {
#pragma unroll
        for (int ni = 0; ni < 4; ni++) {
            int row0 = tile_m + warp_m + mi * 16 + (lane >> 2);
            int col = tile_n + warp_n + ni * 8 + (lane & 3) * 2;
            float b0 = 0.f, b1 = 0.f;
            if (bias) { b0 = bias[col]; b1 = bias[col + 1]; }
            float v0 = acc[mi][ni][0] + b0;
            float v1 = acc[mi][ni][1] + b1;
            float v2 = acc[mi][ni][2] + b0;
            float v3 = acc[mi][ni][3] + b1;
            if (relu) {
                v0 = fmaxf(v0, 0.f); v1 = fmaxf(v1, 0.f);
                v2 = fmaxf(v2, 0.f); v3 = fmaxf(v3, 0.f);
            }
            *(float2*)&C[(long long)row0 * N + col] = make_float2(v0, v1);
            *(float2*)&C[(long long)(row0 + 8) * N + col] = make_float2(v2, v3);
        }
    }
}

// ---------------- weight packing ----------------
__global__ void pack_kernel(const float* __restrict__ Wn, const float* __restrict__ Wn2,
                            const float* __restrict__ lrW1, const float* __restrict__ scrW1,
                            const float* __restrict__ mrW1,
                            const float* __restrict__ lrb1, const float* __restrict__ scrb1,
                            const float* __restrict__ mrb1,
                            float* __restrict__ WnCat, float* __restrict__ W1cat,
                            float* __restrict__ b1cat)
{
    int t = blockIdx.x * blockDim.x + threadIdx.x;
    if (t < 512 * 256) {
        int k = t >> 8, c = t & 255;
        WnCat[t] = (c < 128) ? Wn[k * 128 + c] : Wn2[k * 128 + (c - 128)];
        return;
    }
    int u = t - 512 * 256;
    if (u < 512 * 768) {
        int k = u / 768, c = u % 768;
        float v;
        if (c < 256) v = lrW1[k * 256 + c];
        else if (c < 512) v = scrW1[k * 256 + (c - 256)];
        else v = mrW1[k * 256 + (c - 512)];
        W1cat[u] = v;
        return;
    }
    int v = u - 512 * 768;
    if (v < 768) {
        b1cat[v] = (v < 256) ? lrb1[v] : (v < 512 ? scrb1[v - 256] : mrb1[v - 512]);
    }
}

// ---------------- sparse propagation: node graph ----------------
// H[b,r,:] = rowmask( relu( T1[b,r,:] + sum_c adj[b,r,c] * T1[b,c,:] ) )
// T1 lives in T1XP with row stride 256 (cols 0:128).
__global__ void prop_h_kernel(const float* __restrict__ adj, const float* __restrict__ t1xp,
                              float* __restrict__ H, const int* __restrict__ num_obj)
{
    int b = blockIdx.x >> 7;
    int r = blockIdx.x & 127;
    int t = threadIdx.x;
    int lim = num_obj[b];
    float* orow = H + ((long long)b * 128 + r) * 128;
    if (r >= lim) { orow[t] = 0.f; return; }

    __shared__ int s_idx[128];
    __shared__ float s_val[128];
    __shared__ int s_cnt;
    if (t == 0) s_cnt = 0;
    __syncthreads();

    float a = adj[(((long long)b * 128) + r) * 128 + t];
    if (a != 0.f) {
        int p = atomicAdd(&s_cnt, 1);
        s_idx[p] = t; s_val[p] = a;
    }
    __syncthreads();

    const float* Tb = t1xp + (long long)b * 128 * 256;
    float acc = Tb[r * 256 + t];          // identity term
    int n = s_cnt;
    for (int i = 0; i < n; i++)
        acc = fmaf(s_val[i], Tb[s_idx[i] * 256 + t], acc);
    orow[t] = fmaxf(acc, 0.f);
}

// ---------------- sparse propagation: line graph, fused scatter ----------------
// g[b,m,:] = relu( T2[b,m,:] + sum_c ladj[b,m,c] * T2[b,c,:] )   (m < num_edges)
// then atomicAdd into agg[b, src[m], :]. g is never materialized.
__global__ void prop_g_scatter_kernel(const float* __restrict__ ladj,
                                      const float* __restrict__ T2,
                                      const int* __restrict__ eidx,
                                      const int* __restrict__ num_edges,
                                      float* __restrict__ agg)
{
    int b = blockIdx.x >> 10;
    int m = blockIdx.x & 1023;
    if (m >= num_edges[b]) return;
    int t = threadIdx.x;

    __shared__ int s_idx[1024];
    __shared__ float s_val[1024];
    __shared__ int s_cnt;
    if (t == 0) s_cnt = 0;
    __syncthreads();

    const float* lrow = ladj + (((long long)b * 1024) + m) * 1024;
#pragma unroll
    for (int j = 0; j < 8; j++) {
        int c = t + j * 128;
        float a = lrow[c];
        if (a != 0.f) {
            int p = atomicAdd(&s_cnt, 1);
            s_idx[p] = c; s_val[p] = a;
        }
    }
    __syncthreads();

    const float* Tb = T2 + (long long)b * 1024 * 128;
    float acc = Tb[m * 128 + t];          // identity term
    int n = s_cnt;
    for (int i = 0; i < n; i++)
        acc = fmaf(s_val[i], Tb[s_idx[i] * 128 + t], acc);
    acc = fmaxf(acc, 0.f);

    int s = eidx[b * 2 * Mm + m];
    atomicAdd(&agg[((long long)b * 128 + s) * 128 + t], acc);
}

// ---------------- gathers ----------------
__global__ void gather_eg_kernel(const float* __restrict__ ef, const int* __restrict__ eidx,
                                 const int* __restrict__ num_edges, float* __restrict__ Eg)
{
    int t = blockIdx.x * blockDim.x + threadIdx.x;   // B*M*(DE/4) = 1048576
    int c4 = t & 63;
    int m = (t >> 6) & (Mm - 1);
    int b = t >> 16;
    float4 v = make_float4(0.f, 0.f, 0.f, 0.f);
    if (m < num_edges[b]) {
        int s = eidx[b * 2 * Mm + m];
        int d = eidx[b * 2 * Mm + Mm + m];
        v = ((const float4*)ef)[(((long long)b * Nn + s) * Nn + d) * 64 + c4];
    }
    ((float4*)Eg)[t] = v;
}

__global__ void gather_efp_kernel(const float* __restrict__ ef, const int* __restrict__ pairs,
                                  float* __restrict__ EfP)
{
    int t = blockIdx.x * blockDim.x + threadIdx.x;   // B*P*(DE/4) = 524288
    int c4 = t & 63;
    int p = (t >> 6) & (Pp - 1);
    int b = t >> 15;
    int n0 = pairs[((long long)b * Pp + p) * 2 + 0];
    int n1 = pairs[((long long)b * Pp + p) * 2 + 1];
    ((float4*)EfP)[t] = ((const float4*)ef)[(((long long)b * Nn + n0) * Nn + n1) * 64 + c4];
}

__global__ void zero_kernel(float* __restrict__ p, int n)
{
    int t = blockIdx.x * blockDim.x + threadIdx.x;
    if (t < n) p[t] = 0.f;
}

// ---------------- classifier input assembly ----------------
__global__ void ci_assemble_kernel(const float* __restrict__ h, const float* __restrict__ agg,
                                   const float* __restrict__ t1xp, const float* __restrict__ qp,
                                   const int* __restrict__ pairs, const int* __restrict__ num_obj,
                                   float* __restrict__ ci)
{
    int bp = blockIdx.x;                 // B*P blocks, 128 threads
    int b = bp >> 9;
    int t = threadIdx.x;
    int n0 = pairs[(long long)bp * 2 + 0];
    int n1 = pairs[(long long)bp * 2 + 1];
    int no = num_obj[b];

    const float* hb = h + (long long)b * 128 * 128;
    const float* ab = agg + (long long)b * 128 * 128;
    const float* xb = t1xp + (long long)b * 128 * 256 + 128;  // XP = cols 128:256

    float hv = hb[n0 * 128 + t] + hb[n1 * 128 + t];
    float av = (n0 < no ? ab[n0 * 128 + t] : 0.f) + (n1 < no ? ab[n1 * 128 + t] : 0.f);
    float pm = fmaxf(xb[n0 * 256 + t] + xb[n1 * 256 + t], 0.f);
    float qv = qp[(long long)bp * 128 + t];

    float* o = ci + (long long)bp * 512;
    o[t] = hv;
    o[128 + t] = av;
    o[256 + t] = pm;
    o[384 + t] = qv;
}

// ---------------- layer 2 (small N): one warp per row ----------------
__global__ void layer2_kernel(const float* __restrict__ hid, int ldh, int off,
                              const float* __restrict__ W2, const float* __restrict__ b2,
                              float* __restrict__ out, int outn)
{
    int gw = (blockIdx.x * blockDim.x + threadIdx.x) >> 5;
    int lane = threadIdx.x & 31;
    if (gw >= Bb * Pp) return;
    const float* hr = hid + (long long)gw * ldh + off;
    if (lane < outn) {
        float acc = b2[lane];
#pragma unroll 8
        for (int k = 0; k < HIDc; k++)
            acc = fmaf(hr[k], W2[k * outn + lane], acc);
        out[(long long)gw * outn + lane] = acc;
    }
}

// ---------------- launch ----------------
extern "C" void kernel_launch(void* const* d_in, const int* in_sizes, int n_in,
                              void* d_out, int out_size)
{
    const float* node_features = (const float*)d_in[0];
    const float* edge_features = (const float*)d_in[1];
    const float* adj           = (const float*)d_in[2];
    const float* ladj          = (const float*)d_in[3];
    const int*   edge_index    = (const int*)d_in[4];
    const int*   pairs         = (const int*)d_in[5];
    const int*   num_obj       = (const int*)d_in[6];
    const int*   num_edges     = (const int*)d_in[7];
    const float* Wn  = (const float*)d_in[8];
    const float* We  = (const float*)d_in[9];
    const float* Wn2 = (const float*)d_in[10];
    const float* We2 = (const float*)d_in[11];
    const float* scr_W1 = (const float*)d_in[12];
    const float* scr_b1 = (const float*)d_in[13];
    const float* scr_W2 = (const float*)d_in[14];
    const float* scr_b2 = (const float*)d_in[15];
    const float* lr_W1 = (const float*)d_in[16];
    const float* lr_b1 = (const float*)d_in[17];
    const float* lr_W2 = (const float*)d_in[18];
    const float* lr_b2 = (const float*)d_in[19];
    const float* mr_W1 = (const float*)d_in[20];
    const float* mr_b1 = (const float*)d_in[21];
    const float* mr_W2 = (const float*)d_in[22];
    const float* mr_b2 = (const float*)d_in[23];

    float* out = (float*)d_out;

    float* sc = nullptr;
    cudaGetSymbolAddress((void**)&sc, g_scratch);

    float* T1XP = sc + OFF_T1XP;
    float* EG   = sc + OFF_EG;
    float* T2   = sc + OFF_T2;
    float* H    = sc + OFF_H;
    float* AGG  = sc + OFF_AGG;
    float* EFP  = sc + OFF_EFP;
    float* QP   = sc + OFF_QP;
    float* CI   = sc + OFF_CI;
    float* HIDb = sc + OFF_HID;
    float* WNC  = sc + OFF_WNC;
    float* W1C  = sc + OFF_W1C;
    float* B1C  = sc + OFF_B1C;

    // independent prep
    gather_eg_kernel<<<4096, 256>>>(edge_features, edge_index, num_edges, EG);
    pack_kernel<<<(512 * 256 + 512 * 768 + 768 + 255) / 256, 256>>>(
        Wn, Wn2, lr_W1, scr_W1, mr_W1, lr_b1, scr_b1, mr_b1, WNC, W1C, B1C);
    zero_kernel<<<(Bb * Nn * WEw + 255) / 256, 256>>>(AGG, Bb * Nn * WEw);
    gather_efp_kernel<<<2048, 256>>>(edge_features, pairs, EFP);

    // T1|XP = rowmask(X) @ [Wn|Wn2]   (2048 x 512 x 256)
    gemm_tf32_kernel<<<dim3(256 / 64, 2048 / 64), 128>>>(
        node_features, WNC, nullptr, T1XP, 2048, 256, 512, num_obj, 7, 0);

    // h = rowmask(relu((adj + I) @ T1))  -- sparse
    prop_h_kernel<<<Bb * Nn, 128>>>(adj, T1XP, H, num_obj);

    // T2 = Eg @ We   (16384 x 256 x 128)  (Eg rows already masked-zero)
    gemm_tf32_kernel<<<dim3(128 / 64, 16384 / 64), 128>>>(
        EG, We, nullptr, T2, 16384, 128, 256, nullptr, 0, 0);

    // g = relu((ladj + I) @ T2) fused with scatter-add into agg -- sparse
    prop_g_scatter_kernel<<<Bb * Mm, 128>>>(ladj, T2, edge_index, num_edges, AGG);

    // Q = relu(EfP @ We2)   (8192 x 256 x 128)
    gemm_tf32_kernel<<<dim3(128 / 64, 8192 / 64), 128>>>(
        EFP, We2, nullptr, QP, 8192, 128, 256, nullptr, 0, 1);

    // ci assembly (8192 x 512)
    ci_assemble_kernel<<<Bb * Pp, 128>>>(H, AGG, T1XP, QP, pairs, num_obj, CI);

    // fused head layer-1: HID = relu(CI @ [lrW1|scrW1|mrW1] + b)  (8192 x 512 x 768)
    gemm_tf32_kernel<<<dim3(768 / 64, 8192 / 64), 128>>>(
        CI, W1C, B1C, HIDb, 8192, 768, 512, nullptr, 0, 1);

    // heads layer-2; outputs concatenated (lr, cr, mr)
    float* out_lr = out;
    float* out_cr = out + (long long)Bb * Pp * LR_OUT;
    float* out_mr = out_cr + (long long)Bb * Pp * CR_OUT;

    layer2_kernel<<<(Bb * Pp * 32 + 255) / 256, 256>>>(HIDb, 768, 0,   lr_W2, lr_b2, out_lr, LR_OUT);
    layer2_kernel<<<(Bb * Pp * 32 + 255) / 256, 256>>>(HIDb, 768, 256, scr_W2, scr_b2, out_cr, CR_OUT);
    layer2_kernel<<<(Bb * Pp * 32 + 255) / 256, 256>>>(HIDb, 768, 512, mr_W2, mr_b2, out_mr, MR_OUT);
}

// round 6
// speedup vs baseline: 2.5182x; 1.2086x over previous
#include <cuda_runtime.h>
#include <cstdint>

// ---------------- problem constants ----------------
#define Bb 16
#define Nn 128
#define Mm 1024
#define DNd 512
#define DEe 256
#define WNw 128
#define WEw 128
#define Pp 512
#define HIDc 256
#define LR_OUT 9
#define CR_OUT 6
#define MR_OUT 17

// ---------------- scratch layout (floats) ----------------
// row-offset tables stored as long long at the front (8B aligned)
#define OFF_OFFS 0LL          // 26624 long longs = 53248 floats
#define LLO_N    0            // 2048 entries
#define LLO_E    2048         // 16384 entries
#define LLO_P    18432        // 8192 entries
#define OFF_T1XP 53248LL      // (2048, 256)
#define OFF_T2   577536LL     // (16384, 128)
#define OFF_H    2674688LL    // (2048, 128)
#define OFF_AGG  2936832LL    // (2048, 128)
#define OFF_QP   3198976LL    // (8192, 128)
#define OFF_CI   4247552LL    // (8192, 512)
#define OFF_HID  8441856LL    // (8192, 768)
#define OFF_WNC  14733312LL   // (512, 256)
#define OFF_W1C  14864384LL   // (512, 768)
#define OFF_B1C  15257600LL   // (768)
#define SCRATCH_TOTAL 15258368LL

__device__ float g_scratch[SCRATCH_TOTAL];

// ---------------- tf32 helpers ----------------
__device__ __forceinline__ uint32_t f2tf32(float x) {
    uint32_t r;
    asm("cvt.rna.tf32.f32 %0, %1;" : "=r"(r) : "f"(x));
    return r;
}

__device__ __forceinline__ void mma_tf32(float c[4],
                                         uint32_t a0, uint32_t a1, uint32_t a2, uint32_t a3,
                                         uint32_t b0, uint32_t b1) {
    asm volatile(
        "mma.sync.aligned.m16n8k8.row.col.f32.tf32.tf32.f32 "
        "{%0,%1,%2,%3},{%4,%5,%6,%7},{%8,%9},{%0,%1,%2,%3};"
        : "+f"(c[0]), "+f"(c[1]), "+f"(c[2]), "+f"(c[3])
        : "r"(a0), "r"(a1), "r"(a2), "r"(a3), "r"(b0), "r"(b1));
}

// ---------------- tf32 tensor-core GEMM v2 ----------------
// C[M,N] = act( gatherA[M,K] @ B[K,N] + bias ), row-major.
// A rows fetched via rowoff (element offsets, -1 => zero row). 128x64 tile,
// 256 threads (8 warps, 4x2), double-buffered smem, tf32 conversion at store.
__global__ __launch_bounds__(256)
void gemm2_kernel(const float* __restrict__ A, const float* __restrict__ Bm,
                  const float* __restrict__ bias, float* __restrict__ C,
                  int N, int K, const long long* __restrict__ rowoff, int relu)
{
    __shared__ uint32_t As[2][128][20];
    __shared__ uint32_t Bs[2][16][72];

    const int tile_m = blockIdx.y * 128;
    const int tile_n = blockIdx.x * 64;
    const int tid = threadIdx.x;
    const int warp = tid >> 5;
    const int lane = tid & 31;
    const int warp_m = (warp & 3) * 32;
    const int warp_n = (warp >> 2) * 32;

    // A loader: 2 threads per row, 8 floats each
    const int ar = tid >> 1;
    const int ac8 = (tid & 1) * 8;
    long long aoff = rowoff ? rowoff[tile_m + ar] : (long long)(tile_m + ar) * K;
    const bool aok = (aoff >= 0);
    const float* ap = A + (aok ? aoff : 0) + ac8;

    // B loader: 16 threads per k-row, 4 floats each
    const int br = tid >> 4;
    const int bc4 = (tid & 15) * 4;
    const float* bp = Bm + (long long)br * N + tile_n + bc4;

    float acc[2][4][4];
#pragma unroll
    for (int mi = 0; mi < 2; mi++)
#pragma unroll
        for (int ni = 0; ni < 4; ni++)
#pragma unroll
            for (int q = 0; q < 4; q++) acc[mi][ni][q] = 0.f;

    const int nk = K >> 4;

    // prologue: tile 0
    {
        float4 av0, av1;
        if (aok) { av0 = *(const float4*)(ap); av1 = *(const float4*)(ap + 4); }
        else { av0 = make_float4(0.f,0.f,0.f,0.f); av1 = av0; }
        float4 bv = *(const float4*)(bp);
        uint4 u0 = make_uint4(f2tf32(av0.x), f2tf32(av0.y), f2tf32(av0.z), f2tf32(av0.w));
        uint4 u1 = make_uint4(f2tf32(av1.x), f2tf32(av1.y), f2tf32(av1.z), f2tf32(av1.w));
        *(uint4*)&As[0][ar][ac8] = u0;
        *(uint4*)&As[0][ar][ac8 + 4] = u1;
        *(uint4*)&Bs[0][br][bc4] = make_uint4(f2tf32(bv.x), f2tf32(bv.y), f2tf32(bv.z), f2tf32(bv.w));
    }
    __syncthreads();

    for (int ki = 0; ki < nk; ki++) {
        const int buf = ki & 1;
        const bool more = (ki + 1 < nk);
        float4 pav0, pav1, pbv;
        if (more) {
            const int k0 = (ki + 1) << 4;
            if (aok) { pav0 = *(const float4*)(ap + k0); pav1 = *(const float4*)(ap + k0 + 4); }
            else { pav0 = make_float4(0.f,0.f,0.f,0.f); pav1 = pav0; }
            pbv = *(const float4*)(bp + (long long)k0 * N);
        }

#pragma unroll
        for (int kk = 0; kk < 16; kk += 8) {
            uint32_t af[2][4];
#pragma unroll
            for (int mi = 0; mi < 2; mi++) {
                const int r0 = warp_m + mi * 16 + (lane >> 2);
                const int c0 = kk + (lane & 3);
                af[mi][0] = As[buf][r0][c0];
                af[mi][1] = As[buf][r0 + 8][c0];
                af[mi][2] = As[buf][r0][c0 + 4];
                af[mi][3] = As[buf][r0 + 8][c0 + 4];
            }
            uint32_t bf[4][2];
#pragma unroll
            for (int ni = 0; ni < 4; ni++) {
                const int cc = warp_n + ni * 8 + (lane >> 2);
                const int rr = kk + (lane & 3);
                bf[ni][0] = Bs[buf][rr][cc];
                bf[ni][1] = Bs[buf][rr + 4][cc];
            }
#pragma unroll
            for (int mi = 0; mi < 2; mi++)
#pragma unroll
                for (int ni = 0; ni < 4; ni++)
                    mma_tf32(acc[mi][ni], af[mi][0], af[mi][1], af[mi][2], af[mi][3],
                             bf[ni][0], bf[ni][1]);
        }

        if (more) {
            const int nb = buf ^ 1;
            uint4 u0 = make_uint4(f2tf32(pav0.x), f2tf32(pav0.y), f2tf32(pav0.z), f2tf32(pav0.w));
            uint4 u1 = make_uint4(f2tf32(pav1.x), f2tf32(pav1.y), f2tf32(pav1.z), f2tf32(pav1.w));
            *(uint4*)&As[nb][ar][ac8] = u0;
            *(uint4*)&As[nb][ar][ac8 + 4] = u1;
            *(uint4*)&Bs[nb][br][bc4] = make_uint4(f2tf32(pbv.x), f2tf32(pbv.y), f2tf32(pbv.z), f2tf32(pbv.w));
        }
        __syncthreads();
    }

    // epilogue
#pragma unroll
    for (int mi = 0; mi < 2; mi++) {
#pragma unroll
        for (int ni = 0; ni < 4; ni++) {
            const int row0 = tile_m + warp_m + mi * 16 + (lane >> 2);
            const int col = tile_n + warp_n + ni * 8 + (lane & 3) * 2;
            float b0 = 0.f, b1 = 0.f;
            if (bias) { b0 = bias[col]; b1 = bias[col + 1]; }
            float v0 = acc[mi][ni][0] + b0;
            float v1 = acc[mi][ni][1] + b1;
            float v2 = acc[mi][ni][2] + b0;
            float v3 = acc[mi][ni][3] + b1;
            if (relu) {
                v0 = fmaxf(v0, 0.f); v1 = fmaxf(v1, 0.f);
                v2 = fmaxf(v2, 0.f); v3 = fmaxf(v3, 0.f);
            }
            *(float2*)&C[(long long)row0 * N + col] = make_float2(v0, v1);
            *(float2*)&C[(long long)(row0 + 8) * N + col] = make_float2(v2, v3);
        }
    }
}

// ---------------- prep: row-offset tables + weight packing + AGG zero ----------------
#define PRE_OFFN 0
#define PRE_OFFE 2048
#define PRE_OFFP 18432
#define PRE_WNC  26624
#define PRE_W1C  157696
#define PRE_B1C  550912
#define PRE_AGG  551680
#define PRE_TOT  813824

__global__ void prep_kernel(const int* __restrict__ eidx, const int* __restrict__ pairs,
                            const int* __restrict__ num_obj, const int* __restrict__ num_edges,
                            const float* __restrict__ Wn, const float* __restrict__ Wn2,
                            const float* __restrict__ lrW1, const float* __restrict__ scrW1,
                            const float* __restrict__ mrW1,
                            const float* __restrict__ lrb1, const float* __restrict__ scrb1,
                            const float* __restrict__ mrb1,
                            long long* __restrict__ offs, float* __restrict__ WnCat,
                            float* __restrict__ W1cat, float* __restrict__ b1cat,
                            float* __restrict__ agg)
{
    int t = blockIdx.x * blockDim.x + threadIdx.x;
    if (t >= PRE_TOT) return;
    if (t < PRE_OFFE) {                              // offN
        int b = t >> 7, r = t & 127;
        offs[LLO_N + t] = (r < num_obj[b]) ? (long long)t * DNd : -1LL;
    } else if (t < PRE_OFFP) {                       // offE
        int j = t - PRE_OFFE;
        int b = j >> 10, m = j & 1023;
        long long v = -1LL;
        if (m < num_edges[b]) {
            int s = eidx[b * 2 * Mm + m];
            int d = eidx[b * 2 * Mm + Mm + m];
            v = (((long long)b * Nn + s) * Nn + d) * DEe;
        }
        offs[LLO_E + j] = v;
    } else if (t < PRE_WNC) {                        // offP
        int j = t - PRE_OFFP;
        int b = j >> 9;
        int n0 = pairs[(long long)j * 2 + 0];
        int n1 = pairs[(long long)j * 2 + 1];
        offs[LLO_P + j] = (((long long)b * Nn + n0) * Nn + n1) * DEe;
    } else if (t < PRE_W1C) {                        // WnCat
        int j = t - PRE_WNC;
        int k = j >> 8, c = j & 255;
        WnCat[j] = (c < 128) ? Wn[k * 128 + c] : Wn2[k * 128 + (c - 128)];
    } else if (t < PRE_B1C) {                        // W1cat
        int j = t - PRE_W1C;
        int k = j / 768, c = j % 768;
        float v;
        if (c < 256) v = lrW1[k * 256 + c];
        else if (c < 512) v = scrW1[k * 256 + (c - 256)];
        else v = mrW1[k * 256 + (c - 512)];
        W1cat[j] = v;
    } else if (t < PRE_AGG) {                        // b1cat
        int j = t - PRE_B1C;
        b1cat[j] = (j < 256) ? lrb1[j] : (j < 512 ? scrb1[j - 256] : mrb1[j - 512]);
    } else {                                         // AGG zero
        agg[t - PRE_AGG] = 0.f;
    }
}

// ---------------- sparse propagation: node graph ----------------
__global__ void prop_h_kernel(const float* __restrict__ adj, const float* __restrict__ t1xp,
                              float* __restrict__ H, const int* __restrict__ num_obj)
{
    int b = blockIdx.x >> 7;
    int r = blockIdx.x & 127;
    int t = threadIdx.x;
    int lim = num_obj[b];
    float* orow = H + ((long long)b * 128 + r) * 128;
    if (r >= lim) { orow[t] = 0.f; return; }

    __shared__ int s_idx[128];
    __shared__ float s_val[128];
    __shared__ int s_cnt;
    if (t == 0) s_cnt = 0;
    __syncthreads();

    float a = adj[(((long long)b * 128) + r) * 128 + t];
    if (a != 0.f) {
        int p = atomicAdd(&s_cnt, 1);
        s_idx[p] = t; s_val[p] = a;
    }
    __syncthreads();

    const float* Tb = t1xp + (long long)b * 128 * 256;
    float acc = Tb[r * 256 + t];          // identity term
    int n = s_cnt;
    for (int i = 0; i < n; i++)
        acc = fmaf(s_val[i], Tb[s_idx[i] * 256 + t], acc);
    orow[t] = fmaxf(acc, 0.f);
}

// ---------------- sparse propagation: line graph, fused scatter ----------------
__global__ void prop_g_scatter_kernel(const float* __restrict__ ladj,
                                      const float* __restrict__ T2,
                                      const int* __restrict__ eidx,
                                      const int* __restrict__ num_edges,
                                      float* __restrict__ agg)
{
    int b = blockIdx.x >> 10;
    int m = blockIdx.x & 1023;
    if (m >= num_edges[b]) return;
    int t = threadIdx.x;

    __shared__ int s_idx[1024];
    __shared__ float s_val[1024];
    __shared__ int s_cnt;
    if (t == 0) s_cnt = 0;
    __syncthreads();

    const float* lrow = ladj + (((long long)b * 1024) + m) * 1024;
#pragma unroll
    for (int j = 0; j < 8; j++) {
        int c = t + j * 128;
        float a = lrow[c];
        if (a != 0.f) {
            int p = atomicAdd(&s_cnt, 1);
            s_idx[p] = c; s_val[p] = a;
        }
    }
    __syncthreads();

    const float* Tb = T2 + (long long)b * 1024 * 128;
    float acc = Tb[m * 128 + t];          // identity term
    int n = s_cnt;
    for (int i = 0; i < n; i++)
        acc = fmaf(s_val[i], Tb[s_idx[i] * 128 + t], acc);
    acc = fmaxf(acc, 0.f);

    int s = eidx[b * 2 * Mm + m];
    atomicAdd(&agg[((long long)b * 128 + s) * 128 + t], acc);
}

// ---------------- classifier input assembly ----------------
__global__ void ci_assemble_kernel(const float* __restrict__ h, const float* __restrict__ agg,
                                   const float* __restrict__ t1xp, const float* __restrict__ qp,
                                   const int* __restrict__ pairs, const int* __restrict__ num_obj,
                                   float* __restrict__ ci)
{
    int bp = blockIdx.x;
    int b = bp >> 9;
    int t = threadIdx.x;
    int n0 = pairs[(long long)bp * 2 + 0];
    int n1 = pairs[(long long)bp * 2 + 1];
    int no = num_obj[b];

    const float* hb = h + (long long)b * 128 * 128;
    const float* ab = agg + (long long)b * 128 * 128;
    const float* xb = t1xp + (long long)b * 128 * 256 + 128;  // XP cols

    float hv = hb[n0 * 128 + t] + hb[n1 * 128 + t];
    float av = (n0 < no ? ab[n0 * 128 + t] : 0.f) + (n1 < no ? ab[n1 * 128 + t] : 0.f);
    float pm = fmaxf(xb[n0 * 256 + t] + xb[n1 * 256 + t], 0.f);
    float qv = qp[(long long)bp * 128 + t];

    float* o = ci + (long long)bp * 512;
    o[t] = hv;
    o[128 + t] = av;
    o[256 + t] = pm;
    o[384 + t] = qv;
}

// ---------------- layer 2: all three heads, one warp per row ----------------
__global__ void layer2_kernel(const float* __restrict__ hid,
                              const float* __restrict__ lrW2, const float* __restrict__ lrb2,
                              const float* __restrict__ scrW2, const float* __restrict__ scrb2,
                              const float* __restrict__ mrW2, const float* __restrict__ mrb2,
                              float* __restrict__ out)
{
    int gw = (blockIdx.x * blockDim.x + threadIdx.x) >> 5;
    int lane = threadIdx.x & 31;
    if (gw >= Bb * Pp) return;
    int head = blockIdx.y;

    const float* W2; const float* b2; float* optr; int outn; int off;
    if (head == 0) { W2 = lrW2;  b2 = lrb2;  optr = out;                          outn = LR_OUT; off = 0; }
    else if (head == 1) { W2 = scrW2; b2 = scrb2; optr = out + (long long)Bb*Pp*LR_OUT; outn = CR_OUT; off = 256; }
    else { W2 = mrW2;  b2 = mrb2;  optr = out + (long long)Bb*Pp*(LR_OUT+CR_OUT); outn = MR_OUT; off = 512; }

    const float* hr = hid + (long long)gw * 768 + off;
    if (lane < outn) {
        float acc = b2[lane];
#pragma unroll 8
        for (int k = 0; k < HIDc; k++)
            acc = fmaf(hr[k], W2[k * outn + lane], acc);
        optr[(long long)gw * outn + lane] = acc;
    }
}

// ---------------- launch ----------------
extern "C" void kernel_launch(void* const* d_in, const int* in_sizes, int n_in,
                              void* d_out, int out_size)
{
    const float* node_features = (const float*)d_in[0];
    const float* edge_features = (const float*)d_in[1];
    const float* adj           = (const float*)d_in[2];
    const float* ladj          = (const float*)d_in[3];
    const int*   edge_index    = (const int*)d_in[4];
    const int*   pairs         = (const int*)d_in[5];
    const int*   num_obj       = (const int*)d_in[6];
    const int*   num_edges     = (const int*)d_in[7];
    const float* Wn  = (const float*)d_in[8];
    const float* We  = (const float*)d_in[9];
    const float* Wn2 = (const float*)d_in[10];
    const float* We2 = (const float*)d_in[11];
    const float* scr_W1 = (const float*)d_in[12];
    const float* scr_b1 = (const float*)d_in[13];
    const float* scr_W2 = (const float*)d_in[14];
    const float* scr_b2 = (const float*)d_in[15];
    const float* lr_W1 = (const float*)d_in[16];
    const float* lr_b1 = (const float*)d_in[17];
    const float* lr_W2 = (const float*)d_in[18];
    const float* lr_b2 = (const float*)d_in[19];
    const float* mr_W1 = (const float*)d_in[20];
    const float* mr_b1 = (const float*)d_in[21];
    const float* mr_W2 = (const float*)d_in[22];
    const float* mr_b2 = (const float*)d_in[23];

    float* out = (float*)d_out;

    float* sc = nullptr;
    cudaGetSymbolAddress((void**)&sc, g_scratch);

    long long* OFFS = (long long*)(sc + OFF_OFFS);
    float* T1XP = sc + OFF_T1XP;
    float* T2   = sc + OFF_T2;
    float* H    = sc + OFF_H;
    float* AGG  = sc + OFF_AGG;
    float* QP   = sc + OFF_QP;
    float* CI   = sc + OFF_CI;
    float* HIDb = sc + OFF_HID;
    float* WNC  = sc + OFF_WNC;
    float* W1C  = sc + OFF_W1C;
    float* B1C  = sc + OFF_B1C;

    // 1. prep: offsets + weight packing + AGG zero
    prep_kernel<<<(PRE_TOT + 255) / 256, 256>>>(
        edge_index, pairs, num_obj, num_edges,
        Wn, Wn2, lr_W1, scr_W1, mr_W1, lr_b1, scr_b1, mr_b1,
        OFFS, WNC, W1C, B1C, AGG);

    // 2. T1|XP = rowmask(X) @ [Wn|Wn2]    (2048 x 256 x 512)
    gemm2_kernel<<<dim3(256 / 64, 2048 / 128), 256>>>(
        node_features, WNC, nullptr, T1XP, 256, 512, OFFS + LLO_N, 0);

    // 3. T2 = gather(Eg) @ We             (16384 x 128 x 256)
    gemm2_kernel<<<dim3(128 / 64, 16384 / 128), 256>>>(
        edge_features, We, nullptr, T2, 128, 256, OFFS + LLO_E, 0);

    // 4. h = rowmask(relu((adj + I) @ T1))
    prop_h_kernel<<<Bb * Nn, 128>>>(adj, T1XP, H, num_obj);

    // 5. g = relu((ladj + I) @ T2) fused with scatter into agg
    prop_g_scatter_kernel<<<Bb * Mm, 128>>>(ladj, T2, edge_index, num_edges, AGG);

    // 6. Q = relu(gather(EfP) @ We2)      (8192 x 128 x 256)
    gemm2_kernel<<<dim3(128 / 64, 8192 / 128), 256>>>(
        edge_features, We2, nullptr, QP, 128, 256, OFFS + LLO_P, 1);

    // 7. ci assembly (8192 x 512)
    ci_assemble_kernel<<<Bb * Pp, 128>>>(H, AGG, T1XP, QP, pairs, num_obj, CI);

    // 8. fused head layer-1 (8192 x 768 x 512)
    gemm2_kernel<<<dim3(768 / 64, 8192 / 128), 256>>>(
        CI, W1C, B1C, HIDb, 768, 512, nullptr, 1);

    // 9. layer-2, all heads
    layer2_kernel<<<dim3((Bb * Pp * 32 + 255) / 256, 3), 256>>>(
        HIDb, lr_W2, lr_b2, scr_W2, scr_b2, mr_W2, mr_b2, out);
}

// round 9
// speedup vs baseline: 3.2915x; 1.3071x over previous
#include <cuda_runtime.h>
#include <cuda_fp16.h>
#include <cstdint>

// ---------------- problem constants ----------------
#define Bb 16
#define Nn 128
#define Mm 1024
#define DNd 512
#define DEe 256
#define Pp 512
#define HIDc 256
#define LR_OUT 9
#define CR_OUT 6
#define MR_OUT 17

// ---------------- scratch layout (float units) ----------------
#define OFF_OFFS 0LL          // 26624 long longs = 53248 floats
#define LLO_N    0            // 2048 entries
#define LLO_E    2048         // 16384 entries (edge gather)
#define LLO_P    18432        // 8192 entries (pair gather) -- contiguous after E
#define OFF_T1XP 53248LL      // (2048,256) f32
#define OFF_T2   577536LL     // (16384,128) f32
#define OFF_H    2674688LL    // (2048,128) f32
#define OFF_AGG  2936832LL    // (2048,128) f32
#define OFF_QP   3198976LL    // (8192,128) half
#define OFF_CI   3723264LL    // (8192,512) half
#define OFF_HID  5820416LL    // (8192,768) f32
#define OFF_WNCT 12111872LL   // (256,512) half  [N][K]
#define OFF_WET  12177408LL   // (128,256) half
#define OFF_WE2T 12193792LL   // (128,256) half
#define OFF_W1CT 12210176LL   // (768,512) half
#define OFF_B1C  12406784LL   // 768 f32
#define SCRATCH_TOTAL 12407552LL

__device__ float g_scratch[SCRATCH_TOTAL];

// ---------------- fp16 mma helper ----------------
__device__ __forceinline__ void mma_f16(float c[4],
                                        uint32_t a0, uint32_t a1, uint32_t a2, uint32_t a3,
                                        uint32_t b0, uint32_t b1) {
    asm volatile(
        "mma.sync.aligned.m16n8k16.row.col.f32.f16.f16.f32 "
        "{%0,%1,%2,%3},{%4,%5,%6,%7},{%8,%9},{%0,%1,%2,%3};"
        : "+f"(c[0]), "+f"(c[1]), "+f"(c[2]), "+f"(c[3])
        : "r"(a0), "r"(a1), "r"(a2), "r"(a3), "r"(b0), "r"(b1));
}

__device__ __forceinline__ uint32_t packh2(float lo, float hi) {
    __half2 h = __floats2half2_rn(lo, hi);
    return *(uint32_t*)&h;
}

// ---------------- fp16 tensor-core GEMM ----------------
// C[M,N] = act( A @ Bt^T + bias ). A: fp32 (optionally row-gathered via rowoff,
// -1 => zero row) or fp16 dense (Ah). Bt: half, [N][K] layout. Output fp32 (Cf)
// or half (Ch). 128x128 CTA tile, 256 threads (8 warps, 2m x 4n, warp=64x32),
// double-buffered smem, all conversions outside the inner loop.
// Split mode: blocks with blockIdx.y >= split_y use Bt2/Ch2, relu=1, and output
// rows rebased to 0 (merges two GEMMs sharing one contiguous rowoff table).
__global__ __launch_bounds__(256, 2)
void gemm_h_kernel(const float* __restrict__ A, const __half* __restrict__ Ah,
                   const __half* __restrict__ Bt, const float* __restrict__ bias,
                   float* __restrict__ Cf, __half* __restrict__ Ch,
                   int N, int K, const long long* __restrict__ rowoff, int relu,
                   int split_y, const __half* __restrict__ Bt2, __half* __restrict__ Ch2)
{
    __shared__ __align__(16) __half As[2][128][24];
    __shared__ __align__(16) __half Bs[2][128][24];

    const int my = blockIdx.y;
    const int tile_m = my * 128;
    const int tile_n = blockIdx.x * 128;
    long long crow0 = (long long)tile_m;
    if (split_y && my >= split_y) {
        Bt = Bt2; Ch = Ch2; Cf = nullptr; relu = 1;
        crow0 = (long long)(my - split_y) * 128;
    }

    const int tid = threadIdx.x;
    const int warp = tid >> 5;
    const int lane = tid & 31;
    const int warp_m = (warp & 1) * 64;
    const int warp_n = (warp >> 1) * 32;

    // A loader: 2 threads per row, 8 elements each
    const int ar = tid >> 1;
    const int ac8 = (tid & 1) * 8;
    const float* apf = nullptr;
    const __half* aph = nullptr;
    bool aok = true;
    if (Ah) {
        aph = Ah + (long long)(tile_m + ar) * K + ac8;
    } else {
        long long aoff = rowoff ? rowoff[tile_m + ar] : (long long)(tile_m + ar) * K;
        aok = (aoff >= 0);
        apf = A + (aok ? aoff : 0) + ac8;
    }
    // B loader: 2 threads per output-col row of Bt
    const __half* bp = Bt + (long long)(tile_n + ar) * K + ac8;

    float acc[4][4][4];
#pragma unroll
    for (int mi = 0; mi < 4; mi++)
#pragma unroll
        for (int ni = 0; ni < 4; ni++)
#pragma unroll
            for (int q = 0; q < 4; q++) acc[mi][ni][q] = 0.f;

    const int nk = K >> 4;

    // prologue: tile 0
    {
        uint4 ua;
        if (Ah) ua = *(const uint4*)(aph);
        else if (aok) {
            float4 a0 = *(const float4*)(apf);
            float4 a1 = *(const float4*)(apf + 4);
            ua = make_uint4(packh2(a0.x, a0.y), packh2(a0.z, a0.w),
                            packh2(a1.x, a1.y), packh2(a1.z, a1.w));
        } else ua = make_uint4(0u, 0u, 0u, 0u);
        *(uint4*)&As[0][ar][ac8] = ua;
        *(uint4*)&Bs[0][ar][ac8] = *(const uint4*)(bp);
    }
    __syncthreads();

    for (int ki = 0; ki < nk; ki++) {
        const int buf = ki & 1;
        const bool more = (ki + 1 < nk);
        uint4 pa, pb;
        float4 pf0, pf1;
        if (more) {
            const int k0 = (ki + 1) << 4;
            if (Ah) pa = *(const uint4*)(aph + k0);
            else if (aok) {
                pf0 = *(const float4*)(apf + k0);
                pf1 = *(const float4*)(apf + k0 + 4);
            }
            pb = *(const uint4*)(bp + k0);
        }

        // fragments + MMA
        uint32_t af[4][4];
#pragma unroll
        for (int mi = 0; mi < 4; mi++) {
            const int r0 = warp_m + mi * 16 + (lane >> 2);
            const int c0 = (lane & 3) * 2;
            af[mi][0] = *(const uint32_t*)&As[buf][r0][c0];
            af[mi][1] = *(const uint32_t*)&As[buf][r0 + 8][c0];
            af[mi][2] = *(const uint32_t*)&As[buf][r0][c0 + 8];
            af[mi][3] = *(const uint32_t*)&As[buf][r0 + 8][c0 + 8];
        }
        uint32_t bf[4][2];
#pragma unroll
        for (int ni = 0; ni < 4; ni++) {
            const int cc = warp_n + ni * 8 + (lane >> 2);
            const int rr = (lane & 3) * 2;
            bf[ni][0] = *(const uint32_t*)&Bs[buf][cc][rr];
            bf[ni][1] = *(const uint32_t*)&Bs[buf][cc][rr + 8];
        }
#pragma unroll
        for (int mi = 0; mi < 4; mi++)
#pragma unroll
            for (int ni = 0; ni < 4; ni++)
                mma_f16(acc[mi][ni], af[mi][0], af[mi][1], af[mi][2], af[mi][3],
                        bf[ni][0], bf[ni][1]);

        if (more) {
            const int nb = buf ^ 1;
            uint4 ua;
            if (Ah) ua = pa;
            else if (aok) ua = make_uint4(packh2(pf0.x, pf0.y), packh2(pf0.z, pf0.w),
                                          packh2(pf1.x, pf1.y), packh2(pf1.z, pf1.w));
            else ua = make_uint4(0u, 0u, 0u, 0u);
            *(uint4*)&As[nb][ar][ac8] = ua;
            *(uint4*)&Bs[nb][ar][ac8] = pb;
        }
        __syncthreads();
    }

    // epilogue
#pragma unroll
    for (int mi = 0; mi < 4; mi++) {
#pragma unroll
        for (int ni = 0; ni < 4; ni++) {
            const long long row0 = crow0 + warp_m + mi * 16 + (lane >> 2);
            const int col = tile_n + warp_n + ni * 8 + (lane & 3) * 2;
            float b0 = 0.f, b1 = 0.f;
            if (bias) { b0 = bias[col]; b1 = bias[col + 1]; }
            float v0 = acc[mi][ni][0] + b0;
            float v1 = acc[mi][ni][1] + b1;
            float v2 = acc[mi][ni][2] + b0;
            float v3 = acc[mi][ni][3] + b1;
            if (relu) {
                v0 = fmaxf(v0, 0.f); v1 = fmaxf(v1, 0.f);
                v2 = fmaxf(v2, 0.f); v3 = fmaxf(v3, 0.f);
            }
            if (Ch) {
                __half2 h0 = __floats2half2_rn(v0, v1);
                __half2 h1 = __floats2half2_rn(v2, v3);
                *(__half2*)&Ch[row0 * N + col] = h0;
                *(__half2*)&Ch[(row0 + 8) * N + col] = h1;
            } else {
                *(float2*)&Cf[row0 * N + col] = make_float2(v0, v1);
                *(float2*)&Cf[(row0 + 8) * N + col] = make_float2(v2, v3);
            }
        }
    }
}

// ---------------- prep: offsets + half-transposed weights + bias + AGG zero ----------------
#define PRE_OFFE 2048
#define PRE_OFFP 18432
#define PRE_WNCT 26624
#define PRE_WET  157696
#define PRE_WE2T 190464
#define PRE_W1CT 223232
#define PRE_B1C  616448
#define PRE_AGG  617216
#define PRE_TOT  879360

__global__ void prep_kernel(const int* __restrict__ eidx, const int* __restrict__ pairs,
                            const int* __restrict__ num_obj, const int* __restrict__ num_edges,
                            const float* __restrict__ Wn, const float* __restrict__ Wn2,
                            const float* __restrict__ We, const float* __restrict__ We2,
                            const float* __restrict__ lrW1, const float* __restrict__ scrW1,
                            const float* __restrict__ mrW1,
                            const float* __restrict__ lrb1, const float* __restrict__ scrb1,
                            const float* __restrict__ mrb1,
                            long long* __restrict__ offs,
                            __half* __restrict__ WnT, __half* __restrict__ WeT,
                            __half* __restrict__ We2T, __half* __restrict__ W1T,
                            float* __restrict__ b1cat, float* __restrict__ agg)
{
    int t = blockIdx.x * blockDim.x + threadIdx.x;
    if (t >= PRE_TOT) return;
    if (t < PRE_OFFE) {                              // node row offsets
        int b = t >> 7, r = t & 127;
        offs[LLO_N + t] = (r < num_obj[b]) ? (long long)t * DNd : -1LL;
    } else if (t < PRE_OFFP) {                       // edge gather offsets
        int j = t - PRE_OFFE;
        int b = j >> 10, m = j & 1023;
        long long v = -1LL;
        if (m < num_edges[b]) {
            int s = eidx[b * 2 * Mm + m];
            int d = eidx[b * 2 * Mm + Mm + m];
            v = (((long long)b * Nn + s) * Nn + d) * DEe;
        }
        offs[LLO_E + j] = v;
    } else if (t < PRE_WNCT) {                       // pair gather offsets
        int j = t - PRE_OFFP;
        int b = j >> 9;
        int n0 = pairs[(long long)j * 2 + 0];
        int n1 = pairs[(long long)j * 2 + 1];
        offs[LLO_P + j] = (((long long)b * Nn + n0) * Nn + n1) * DEe;
    } else if (t < PRE_WET) {                        // [Wn|Wn2]^T -> half [256][512]
        int j = t - PRE_WNCT;
        int c = j >> 9, k = j & 511;
        float v = (c < 128) ? Wn[k * 128 + c] : Wn2[k * 128 + (c - 128)];
        WnT[j] = __float2half(v);
    } else if (t < PRE_WE2T) {                       // We^T -> half [128][256]
        int j = t - PRE_WET;
        int c = j >> 8, k = j & 255;
        WeT[j] = __float2half(We[k * 128 + c]);
    } else if (t < PRE_W1CT) {                       // We2^T -> half [128][256]
        int j = t - PRE_WE2T;
        int c = j >> 8, k = j & 255;
        We2T[j] = __float2half(We2[k * 128 + c]);
    } else if (t < PRE_B1C) {                        // [lr|scr|mr]W1^T -> half [768][512]
        int j = t - PRE_W1CT;
        int c = j >> 9, k = j & 511;
        float v;
        if (c < 256) v = lrW1[k * 256 + c];
        else if (c < 512) v = scrW1[k * 256 + (c - 256)];
        else v = mrW1[k * 256 + (c - 512)];
        W1T[j] = __float2half(v);
    } else if (t < PRE_AGG) {                        // bias concat
        int j = t - PRE_B1C;
        b1cat[j] = (j < 256) ? lrb1[j] : (j < 512 ? scrb1[j - 256] : mrb1[j - 512]);
    } else {                                         // AGG zero
        agg[t - PRE_AGG] = 0.f;
    }
}

// ---------------- sparse propagation: node graph ----------------
__global__ void prop_h_kernel(const float* __restrict__ adj, const float* __restrict__ t1xp,
                              float* __restrict__ H, const int* __restrict__ num_obj)
{
    int b = blockIdx.x >> 7;
    int r = blockIdx.x & 127;
    int t = threadIdx.x;
    int lim = num_obj[b];
    float* orow = H + ((long long)b * 128 + r) * 128;
    if (r >= lim) { orow[t] = 0.f; return; }

    __shared__ int s_idx[128];
    __shared__ float s_val[128];
    __shared__ int s_cnt;
    if (t == 0) s_cnt = 0;
    __syncthreads();

    float a = adj[(((long long)b * 128) + r) * 128 + t];
    if (a != 0.f) {
        int p = atomicAdd(&s_cnt, 1);
        s_idx[p] = t; s_val[p] = a;
    }
    __syncthreads();

    const float* Tb = t1xp + (long long)b * 128 * 256;
    float acc = Tb[r * 256 + t];          // identity term
    int n = s_cnt;
    for (int i = 0; i < n; i++)
        acc = fmaf(s_val[i], Tb[s_idx[i] * 256 + t], acc);
    orow[t] = fmaxf(acc, 0.f);
}

// ---------------- sparse propagation: line graph, fused scatter ----------------
__global__ void prop_g_scatter_kernel(const float* __restrict__ ladj,
                                      const float* __restrict__ T2,
                                      const int* __restrict__ eidx,
                                      const int* __restrict__ num_edges,
                                      float* __restrict__ agg)
{
    int b = blockIdx.x >> 10;
    int m = blockIdx.x & 1023;
    if (m >= num_edges[b]) return;
    int t = threadIdx.x;

    __shared__ int s_idx[1024];
    __shared__ float s_val[1024];
    __shared__ int s_cnt;
    if (t == 0) s_cnt = 0;
    __syncthreads();

    const float* lrow = ladj + (((long long)b * 1024) + m) * 1024;
#pragma unroll
    for (int j = 0; j < 8; j++) {
        int c = t + j * 128;
        float a = lrow[c];
        if (a != 0.f) {
            int p = atomicAdd(&s_cnt, 1);
            s_idx[p] = c; s_val[p] = a;
        }
    }
    __syncthreads();

    const float* Tb = T2 + (long long)b * 1024 * 128;
    float acc = Tb[m * 128 + t];          // identity term
    int n = s_cnt;
    for (int i = 0; i < n; i++)
        acc = fmaf(s_val[i], Tb[s_idx[i] * 128 + t], acc);
    acc = fmaxf(acc, 0.f);

    int s = eidx[b * 2 * Mm + m];
    atomicAdd(&agg[((long long)b * 128 + s) * 128 + t], acc);
}

// ---------------- classifier input assembly (half output) ----------------
__global__ void ci_assemble_kernel(const float* __restrict__ h, const float* __restrict__ agg,
                                   const float* __restrict__ t1xp, const __half* __restrict__ qp,
                                   const int* __restrict__ pairs, const int* __restrict__ num_obj,
                                   __half* __restrict__ ci)
{
    int bp = blockIdx.x;
    int b = bp >> 9;
    int t = threadIdx.x;
    int n0 = pairs[(long long)bp * 2 + 0];
    int n1 = pairs[(long long)bp * 2 + 1];
    int no = num_obj[b];

    const float* hb = h + (long long)b * 128 * 128;
    const float* ab = agg + (long long)b * 128 * 128;
    const float* xb = t1xp + (long long)b * 128 * 256 + 128;  // XP cols

    float hv = hb[n0 * 128 + t] + hb[n1 * 128 + t];
    float av = (n0 < no ? ab[n0 * 128 + t] : 0.f) + (n1 < no ? ab[n1 * 128 + t] : 0.f);
    float pm = fmaxf(xb[n0 * 256 + t] + xb[n1 * 256 + t], 0.f);
    float qv = __half2float(qp[(long long)bp * 128 + t]);

    __half* o = ci + (long long)bp * 512;
    o[t] = __float2half(hv);
    o[128 + t] = __float2half(av);
    o[256 + t] = __float2half(pm);
    o[384 + t] = __float2half(qv);
}

// ---------------- layer 2: all three heads, one warp per row ----------------
__global__ void layer2_kernel(const float* __restrict__ hid,
                              const float* __restrict__ lrW2, const float* __restrict__ lrb2,
                              const float* __restrict__ scrW2, const float* __restrict__ scrb2,
                              const float* __restrict__ mrW2, const float* __restrict__ mrb2,
                              float* __restrict__ out)
{
    int gw = (blockIdx.x * blockDim.x + threadIdx.x) >> 5;
    int lane = threadIdx.x & 31;
    if (gw >= Bb * Pp) return;
    int head = blockIdx.y;

    const float* W2; const float* b2; float* optr; int outn; int off;
    if (head == 0) { W2 = lrW2;  b2 = lrb2;  optr = out;                          outn = LR_OUT; off = 0; }
    else if (head == 1) { W2 = scrW2; b2 = scrb2; optr = out + (long long)Bb*Pp*LR_OUT; outn = CR_OUT; off = 256; }
    else { W2 = mrW2;  b2 = mrb2;  optr = out + (long long)Bb*Pp*(LR_OUT+CR_OUT); outn = MR_OUT; off = 512; }

    const float* hr = hid + (long long)gw * 768 + off;
    if (lane < outn) {
        float acc = b2[lane];
#pragma unroll 8
        for (int k = 0; k < HIDc; k++)
            acc = fmaf(hr[k], W2[k * outn + lane], acc);
        optr[(long long)gw * outn + lane] = acc;
    }
}

// ---------------- launch ----------------
extern "C" void kernel_launch(void* const* d_in, const int* in_sizes, int n_in,
                              void* d_out, int out_size)
{
    const float* node_features = (const float*)d_in[0];
    const float* edge_features = (const float*)d_in[1];
    const float* adj           = (const float*)d_in[2];
    const float* ladj          = (const float*)d_in[3];
    const int*   edge_index    = (const int*)d_in[4];
    const int*   pairs         = (const int*)d_in[5];
    const int*   num_obj       = (const int*)d_in[6];
    const int*   num_edges     = (const int*)d_in[7];
    const float* Wn  = (const float*)d_in[8];
    const float* We  = (const float*)d_in[9];
    const float* Wn2 = (const float*)d_in[10];
    const float* We2 = (const float*)d_in[11];
    const float* scr_W1 = (const float*)d_in[12];
    const float* scr_b1 = (const float*)d_in[13];
    const float* scr_W2 = (const float*)d_in[14];
    const float* scr_b2 = (const float*)d_in[15];
    const float* lr_W1 = (const float*)d_in[16];
    const float* lr_b1 = (const float*)d_in[17];
    const float* lr_W2 = (const float*)d_in[18];
    const float* lr_b2 = (const float*)d_in[19];
    const float* mr_W1 = (const float*)d_in[20];
    const float* mr_b1 = (const float*)d_in[21];
    const float* mr_W2 = (const float*)d_in[22];
    const float* mr_b2 = (const float*)d_in[23];

    float* out = (float*)d_out;

    float* sc = nullptr;
    cudaGetSymbolAddress((void**)&sc, g_scratch);

    long long* OFFS = (long long*)(sc + OFF_OFFS);
    float*  T1XP = sc + OFF_T1XP;
    float*  T2   = sc + OFF_T2;
    float*  H    = sc + OFF_H;
    float*  AGG  = sc + OFF_AGG;
    __half* QPh  = (__half*)(sc + OFF_QP);
    __half* CIh  = (__half*)(sc + OFF_CI);
    float*  HIDb = sc + OFF_HID;
    __half* WNT  = (__half*)(sc + OFF_WNCT);
    __half* WET  = (__half*)(sc + OFF_WET);
    __half* WE2T = (__half*)(sc + OFF_WE2T);
    __half* W1T  = (__half*)(sc + OFF_W1CT);
    float*  B1C  = sc + OFF_B1C;

    // 1. prep
    prep_kernel<<<(PRE_TOT + 255) / 256, 256>>>(
        edge_index, pairs, num_obj, num_edges,
        Wn, Wn2, We, We2, lr_W1, scr_W1, mr_W1, lr_b1, scr_b1, mr_b1,
        OFFS, WNT, WET, WE2T, W1T, B1C, AGG);

    // 2. T1|XP = rowmask(X) @ [Wn|Wn2]    (2048 x 256 x 512)
    gemm_h_kernel<<<dim3(2, 16), 256>>>(
        node_features, nullptr, WNT, nullptr, T1XP, nullptr,
        256, 512, OFFS + LLO_N, 0, 0, nullptr, nullptr);

    // 3. merged: T2 = gatherE @ We (rows 0..16383) ; QP = relu(gatherP @ We2) (rows 16384..)
    gemm_h_kernel<<<dim3(1, 192), 256>>>(
        edge_features, nullptr, WET, nullptr, T2, nullptr,
        128, 256, OFFS + LLO_E, 0, 128, WE2T, QPh);

    // 4. h = rowmask(relu((adj + I) @ T1))
    prop_h_kernel<<<Bb * Nn, 128>>>(adj, T1XP, H, num_obj);

    // 5. g = relu((ladj + I) @ T2) fused with scatter into agg
    prop_g_scatter_kernel<<<Bb * Mm, 128>>>(ladj, T2, edge_index, num_edges, AGG);

    // 6. ci assembly (8192 x 512, half)
    ci_assemble_kernel<<<Bb * Pp, 128>>>(H, AGG, T1XP, QPh, pairs, num_obj, CIh);

    // 7. fused head layer-1: HID = relu(CI @ W1cat + b)   (8192 x 768 x 512)
    gemm_h_kernel<<<dim3(6, 64), 256>>>(
        nullptr, CIh, W1T, B1C, HIDb, nullptr,
        768, 512, nullptr, 1, 0, nullptr, nullptr);

    // 8. layer-2, all heads
    layer2_kernel<<<dim3((Bb * Pp * 32 + 255) / 256, 3), 256>>>(
        HIDb, lr_W2, lr_b2, scr_W2, scr_b2, mr_W2, mr_b2, out);
}

// round 10
// speedup vs baseline: 5.1247x; 1.5570x over previous
#include <cuda_runtime.h>
#include <cuda_fp16.h>
#include <cstdint>

// ---------------- problem constants ----------------
#define Bb 16
#define Nn 128
#define Mm 1024
#define DNd 512
#define DEe 256
#define Pp 512
#define LR_OUT 9
#define CR_OUT 6
#define MR_OUT 17

// ---------------- scratch layout (float units) ----------------
#define OFF_OFFS 0LL          // 26624 long longs = 53248 floats
#define LLO_N    0
#define LLO_E    2048
#define LLO_P    18432
#define OFF_T1XP 53248LL      // (2048,256) f32
#define OFF_T2   577536LL     // (16384,128) f32
#define OFF_H    2674688LL    // (2048,128) f32
#define OFF_AGG  2936832LL    // (2048,128) f32
#define OFF_QP   3198976LL    // (8192,128) half
#define OFF_CI   3723264LL    // (8192,512) half
#define OFF_HID  5820416LL    // (8192,768) half
#define OFF_WNT  8966144LL    // (256,512) half
#define OFF_WET  9031680LL    // (128,256) half
#define OFF_WE2T 9048064LL    // (128,256) half
#define OFF_W1T  9064448LL    // (768,512) half
#define OFF_W2T  9261056LL    // (32,768) half (block-diagonal)
#define OFF_B1C  9273344LL    // 768 f32
#define OFF_B2C  9274112LL    // 32 f32
#define SCRATCH_TOTAL 9274144LL

__device__ float g_scratch[SCRATCH_TOTAL];

// ---------------- mma / ldmatrix helpers ----------------
__device__ __forceinline__ void mma_f16(float c[4],
                                        uint32_t a0, uint32_t a1, uint32_t a2, uint32_t a3,
                                        uint32_t b0, uint32_t b1) {
    asm volatile(
        "mma.sync.aligned.m16n8k16.row.col.f32.f16.f16.f32 "
        "{%0,%1,%2,%3},{%4,%5,%6,%7},{%8,%9},{%0,%1,%2,%3};"
        : "+f"(c[0]), "+f"(c[1]), "+f"(c[2]), "+f"(c[3])
        : "r"(a0), "r"(a1), "r"(a2), "r"(a3), "r"(b0), "r"(b1));
}

__device__ __forceinline__ void ldsm_x4(uint32_t& r0, uint32_t& r1, uint32_t& r2, uint32_t& r3,
                                        uint32_t addr) {
    asm volatile("ldmatrix.sync.aligned.m8n8.x4.shared.b16 {%0,%1,%2,%3}, [%4];"
                 : "=r"(r0), "=r"(r1), "=r"(r2), "=r"(r3) : "r"(addr));
}

__device__ __forceinline__ uint32_t packh2(float lo, float hi) {
    __half2 h = __floats2half2_rn(lo, hi);
    return *(uint32_t*)&h;
}

__device__ __forceinline__ uint32_t smem_u32(const void* p) {
    return (uint32_t)__cvta_generic_to_shared(p);
}

// ============================================================================
// Segmented GEMM: three GEMMs in one launch, 128x64 tiles, 256 thr (8 warps 4x2)
//   seg0 (blk 0..63):    T1XP = gatherN(nf) @ WNT^T   M=2048 N=256 K=512  f32
//   seg1 (blk 64..319):  T2   = gatherE(ef) @ WET^T   M=16384 N=128 K=256 f32
//   seg2 (blk 320..447): QP   = relu(gatherP(ef) @ WE2T^T) M=8192 N=128 K=256 half
// ============================================================================
__global__ __launch_bounds__(256, 2)
void gemm_seg_kernel(const float* __restrict__ nf, const float* __restrict__ ef,
                     const __half* __restrict__ WNT, const __half* __restrict__ WET,
                     const __half* __restrict__ WE2T, const long long* __restrict__ offs,
                     float* __restrict__ T1XP, float* __restrict__ T2, __half* __restrict__ QP)
{
    __shared__ __align__(16) __half As[2][128][24];
    __shared__ __align__(16) __half Bs[2][64][24];

    const int bid = blockIdx.x;
    const float* A; const __half* Bt; float* Cf = nullptr; __half* Ch = nullptr;
    const long long* ro; int K, N, mt, nt, relu = 0;
    if (bid < 64)       { mt = bid >> 2;           nt = bid & 3; K = 512; N = 256; A = nf; Bt = WNT;  Cf = T1XP; ro = offs + LLO_N; }
    else if (bid < 320) { int j = bid - 64;  mt = j >> 1; nt = j & 1; K = 256; N = 128; A = ef; Bt = WET;  Cf = T2;   ro = offs + LLO_E; }
    else                { int j = bid - 320; mt = j >> 1; nt = j & 1; K = 256; N = 128; A = ef; Bt = WE2T; Ch = QP;   ro = offs + LLO_P; relu = 1; }

    const int tile_m = mt * 128;
    const int tile_n = nt * 64;
    const int tid = threadIdx.x;
    const int warp = tid >> 5;
    const int lane = tid & 31;
    const int warp_m = (warp & 3) * 32;
    const int warp_n = (warp >> 2) * 32;

    // A loader: 2 threads/row, 8 floats
    const int ar = tid >> 1;
    const int ac8 = (tid & 1) * 8;
    long long aoff = ro[tile_m + ar];
    const bool aok = (aoff >= 0);
    const float* apf = A + (aok ? aoff : 0) + ac8;
    // B loader: threads 0..127, 2/row
    const bool bldr = (tid < 128);
    const __half* bp = bldr ? (Bt + (long long)(tile_n + ar) * K + ac8) : Bt;

    // ldmatrix addresses
    const uint32_t a_base = smem_u32(&As[0][0][0]);
    const uint32_t b_base = smem_u32(&Bs[0][0][0]);
    const int li = lane >> 3, lr = lane & 7;
    uint32_t a_addr[2], b_addr[2];
#pragma unroll
    for (int mi = 0; mi < 2; mi++)
        a_addr[mi] = a_base + ((warp_m + mi * 16 + (li & 1) * 8 + lr) * 24 + (li >> 1) * 8) * 2;
#pragma unroll
    for (int j = 0; j < 2; j++)
        b_addr[j] = b_base + ((warp_n + (2 * j + (li >> 1)) * 8 + lr) * 24 + (li & 1) * 8) * 2;

    float acc[2][4][4];
#pragma unroll
    for (int mi = 0; mi < 2; mi++)
#pragma unroll
        for (int ni = 0; ni < 4; ni++)
#pragma unroll
            for (int q = 0; q < 4; q++) acc[mi][ni][q] = 0.f;

    const int nk = K >> 4;

    // prologue
    {
        uint4 ua = make_uint4(0u, 0u, 0u, 0u);
        if (aok) {
            float4 a0 = *(const float4*)(apf);
            float4 a1 = *(const float4*)(apf + 4);
            ua = make_uint4(packh2(a0.x, a0.y), packh2(a0.z, a0.w),
                            packh2(a1.x, a1.y), packh2(a1.z, a1.w));
        }
        *(uint4*)&As[0][ar][ac8] = ua;
        if (bldr) *(uint4*)&Bs[0][ar][ac8] = *(const uint4*)(bp);
    }
    __syncthreads();

    for (int ki = 0; ki < nk; ki++) {
        const int buf = ki & 1;
        const bool more = (ki + 1 < nk);
        float4 pf0, pf1; uint4 pb;
        if (more) {
            const int k0 = (ki + 1) << 4;
            if (aok) { pf0 = *(const float4*)(apf + k0); pf1 = *(const float4*)(apf + k0 + 4); }
            if (bldr) pb = *(const uint4*)(bp + k0);
        }

        uint32_t a[2][4], b[4][2];
        const uint32_t abuf = buf * 6144u, bbuf = buf * 3072u;
#pragma unroll
        for (int mi = 0; mi < 2; mi++)
            ldsm_x4(a[mi][0], a[mi][1], a[mi][2], a[mi][3], a_addr[mi] + abuf);
        ldsm_x4(b[0][0], b[0][1], b[1][0], b[1][1], b_addr[0] + bbuf);
        ldsm_x4(b[2][0], b[2][1], b[3][0], b[3][1], b_addr[1] + bbuf);
#pragma unroll
        for (int mi = 0; mi < 2; mi++)
#pragma unroll
            for (int ni = 0; ni < 4; ni++)
                mma_f16(acc[mi][ni], a[mi][0], a[mi][1], a[mi][2], a[mi][3],
                        b[ni][0], b[ni][1]);

        if (more) {
            const int nb = buf ^ 1;
            uint4 ua = make_uint4(0u, 0u, 0u, 0u);
            if (aok) ua = make_uint4(packh2(pf0.x, pf0.y), packh2(pf0.z, pf0.w),
                                     packh2(pf1.x, pf1.y), packh2(pf1.z, pf1.w));
            *(uint4*)&As[nb][ar][ac8] = ua;
            if (bldr) *(uint4*)&Bs[nb][ar][ac8] = pb;
        }
        __syncthreads();
    }

#pragma unroll
    for (int mi = 0; mi < 2; mi++) {
#pragma unroll
        for (int ni = 0; ni < 4; ni++) {
            const long long row0 = tile_m + warp_m + mi * 16 + (lane >> 2);
            const int col = tile_n + warp_n + ni * 8 + (lane & 3) * 2;
            float v0 = acc[mi][ni][0], v1 = acc[mi][ni][1];
            float v2 = acc[mi][ni][2], v3 = acc[mi][ni][3];
            if (relu) {
                v0 = fmaxf(v0, 0.f); v1 = fmaxf(v1, 0.f);
                v2 = fmaxf(v2, 0.f); v3 = fmaxf(v3, 0.f);
            }
            if (Ch) {
                *(__half2*)&Ch[row0 * N + col] = __floats2half2_rn(v0, v1);
                *(__half2*)&Ch[(row0 + 8) * N + col] = __floats2half2_rn(v2, v3);
            } else {
                *(float2*)&Cf[row0 * N + col] = make_float2(v0, v1);
                *(float2*)&Cf[(row0 + 8) * N + col] = make_float2(v2, v3);
            }
        }
    }
}

// ============================================================================
// HID GEMM: HID = relu(CI @ W1T^T + b1), 8192x768x512, half in/out, 128x128 tiles
// ============================================================================
__global__ __launch_bounds__(256, 2)
void gemm_hid_kernel(const __half* __restrict__ CI, const __half* __restrict__ W1T,
                     const float* __restrict__ b1, __half* __restrict__ HID)
{
    __shared__ __align__(16) __half As[2][128][24];
    __shared__ __align__(16) __half Bs[2][128][24];

    const int tile_m = blockIdx.y * 128;
    const int tile_n = blockIdx.x * 128;
    const int tid = threadIdx.x;
    const int warp = tid >> 5;
    const int lane = tid & 31;
    const int warp_m = (warp & 1) * 64;
    const int warp_n = (warp >> 1) * 32;

    const int ar = tid >> 1;
    const int ac8 = (tid & 1) * 8;
    const __half* ap = CI + (long long)(tile_m + ar) * 512 + ac8;
    const __half* bp = W1T + (long long)(tile_n + ar) * 512 + ac8;

    const uint32_t a_base = smem_u32(&As[0][0][0]);
    const uint32_t b_base = smem_u32(&Bs[0][0][0]);
    const int li = lane >> 3, lr = lane & 7;
    uint32_t a_addr[4], b_addr[2];
#pragma unroll
    for (int mi = 0; mi < 4; mi++)
        a_addr[mi] = a_base + ((warp_m + mi * 16 + (li & 1) * 8 + lr) * 24 + (li >> 1) * 8) * 2;
#pragma unroll
    for (int j = 0; j < 2; j++)
        b_addr[j] = b_base + ((warp_n + (2 * j + (li >> 1)) * 8 + lr) * 24 + (li & 1) * 8) * 2;

    float acc[4][4][4];
#pragma unroll
    for (int mi = 0; mi < 4; mi++)
#pragma unroll
        for (int ni = 0; ni < 4; ni++)
#pragma unroll
            for (int q = 0; q < 4; q++) acc[mi][ni][q] = 0.f;

    *(uint4*)&As[0][ar][ac8] = *(const uint4*)(ap);
    *(uint4*)&Bs[0][ar][ac8] = *(const uint4*)(bp);
    __syncthreads();

#pragma unroll 2
    for (int ki = 0; ki < 32; ki++) {
        const int buf = ki & 1;
        const bool more = (ki + 1 < 32);
        uint4 pa, pb;
        if (more) {
            const int k0 = (ki + 1) << 4;
            pa = *(const uint4*)(ap + k0);
            pb = *(const uint4*)(bp + k0);
        }

        uint32_t a[4][4], b[4][2];
        const uint32_t sb = buf * 6144u;
#pragma unroll
        for (int mi = 0; mi < 4; mi++)
            ldsm_x4(a[mi][0], a[mi][1], a[mi][2], a[mi][3], a_addr[mi] + sb);
        ldsm_x4(b[0][0], b[0][1], b[1][0], b[1][1], b_addr[0] + sb);
        ldsm_x4(b[2][0], b[2][1], b[3][0], b[3][1], b_addr[1] + sb);
#pragma unroll
        for (int mi = 0; mi < 4; mi++)
#pragma unroll
            for (int ni = 0; ni < 4; ni++)
                mma_f16(acc[mi][ni], a[mi][0], a[mi][1], a[mi][2], a[mi][3],
                        b[ni][0], b[ni][1]);

        if (more) {
            const int nb = buf ^ 1;
            *(uint4*)&As[nb][ar][ac8] = pa;
            *(uint4*)&Bs[nb][ar][ac8] = pb;
        }
        __syncthreads();
    }

#pragma unroll
    for (int mi = 0; mi < 4; mi++) {
#pragma unroll
        for (int ni = 0; ni < 4; ni++) {
            const long long row0 = tile_m + warp_m + mi * 16 + (lane >> 2);
            const int col = tile_n + warp_n + ni * 8 + (lane & 3) * 2;
            const float b0 = b1[col], b1v = b1[col + 1];
            float v0 = fmaxf(acc[mi][ni][0] + b0, 0.f);
            float v1 = fmaxf(acc[mi][ni][1] + b1v, 0.f);
            float v2 = fmaxf(acc[mi][ni][2] + b0, 0.f);
            float v3 = fmaxf(acc[mi][ni][3] + b1v, 0.f);
            *(__half2*)&HID[row0 * 768 + col] = __floats2half2_rn(v0, v1);
            *(__half2*)&HID[(row0 + 8) * 768 + col] = __floats2half2_rn(v2, v3);
        }
    }
}

// ============================================================================
// Layer-2 GEMM: out = HID @ W2T^T + b2, 8192x32x768, block-diag W2, scatter epi
// 64x32 tile, 128 thr (4 warps, each 16x32)
// ============================================================================
__global__ __launch_bounds__(128)
void gemm_l2_kernel(const __half* __restrict__ HID, const __half* __restrict__ W2T,
                    const float* __restrict__ b2, float* __restrict__ out)
{
    __shared__ __align__(16) __half As[2][64][24];
    __shared__ __align__(16) __half Bs[2][32][24];

    const int tile_m = blockIdx.x * 64;
    const int tid = threadIdx.x;
    const int warp = tid >> 5;
    const int lane = tid & 31;
    const int warp_m = warp * 16;

    const int ar = tid >> 1;
    const int ac8 = (tid & 1) * 8;
    const __half* ap = HID + (long long)(tile_m + ar) * 768 + ac8;
    const bool bldr = (tid < 64);
    const __half* bp = bldr ? (W2T + (long long)ar * 768 + ac8) : W2T;

    const uint32_t a_base = smem_u32(&As[0][0][0]);
    const uint32_t b_base = smem_u32(&Bs[0][0][0]);
    const int li = lane >> 3, lr = lane & 7;
    const uint32_t a_addr = a_base + ((warp_m + (li & 1) * 8 + lr) * 24 + (li >> 1) * 8) * 2;
    uint32_t b_addr[2];
#pragma unroll
    for (int j = 0; j < 2; j++)
        b_addr[j] = b_base + (((2 * j + (li >> 1)) * 8 + lr) * 24 + (li & 1) * 8) * 2;

    float acc[4][4];
#pragma unroll
    for (int ni = 0; ni < 4; ni++)
#pragma unroll
        for (int q = 0; q < 4; q++) acc[ni][q] = 0.f;

    *(uint4*)&As[0][ar][ac8] = *(const uint4*)(ap);
    if (bldr) *(uint4*)&Bs[0][ar][ac8] = *(const uint4*)(bp);
    __syncthreads();

    for (int ki = 0; ki < 48; ki++) {
        const int buf = ki & 1;
        const bool more = (ki + 1 < 48);
        uint4 pa, pb;
        if (more) {
            const int k0 = (ki + 1) << 4;
            pa = *(const uint4*)(ap + k0);
            if (bldr) pb = *(const uint4*)(bp + k0);
        }

        uint32_t a[4], b[4][2];
        const uint32_t asb = buf * 3072u, bsb = buf * 1536u;
        ldsm_x4(a[0], a[1], a[2], a[3], a_addr + asb);
        ldsm_x4(b[0][0], b[0][1], b[1][0], b[1][1], b_addr[0] + bsb);
        ldsm_x4(b[2][0], b[2][1], b[3][0], b[3][1], b_addr[1] + bsb);
#pragma unroll
        for (int ni = 0; ni < 4; ni++)
            mma_f16(acc[ni], a[0], a[1], a[2], a[3], b[ni][0], b[ni][1]);

        if (more) {
            const int nb = buf ^ 1;
            *(uint4*)&As[nb][ar][ac8] = pa;
            if (bldr) *(uint4*)&Bs[nb][ar][ac8] = pb;
        }
        __syncthreads();
    }

    // scatter epilogue: cols 0-8 -> lr, 9-14 -> cr, 15-31 -> mr
    float* out_cr = out + (long long)Bb * Pp * LR_OUT;
    float* out_mr = out_cr + (long long)Bb * Pp * CR_OUT;
#pragma unroll
    for (int ni = 0; ni < 4; ni++) {
        const long long r0 = tile_m + warp_m + (lane >> 2);
        const int c0 = ni * 8 + (lane & 3) * 2;
#pragma unroll
        for (int q = 0; q < 4; q++) {
            const long long row = r0 + (q >> 1) * 8;
            const int c = c0 + (q & 1);
            const float v = acc[ni][q] + b2[c];
            if (c < 9)       out[row * 9 + c] = v;
            else if (c < 15) out_cr[row * 6 + (c - 9)] = v;
            else             out_mr[row * 17 + (c - 15)] = v;
        }
    }
}

// ---------------- prep ----------------
#define PRE_OFFE 2048
#define PRE_OFFP 18432
#define PRE_WNT  26624
#define PRE_WET  157696
#define PRE_WE2T 190464
#define PRE_W1T  223232
#define PRE_W2T  616448
#define PRE_B1   641024
#define PRE_B2   641792
#define PRE_AGG  641824
#define PRE_TOT  903968

__global__ void prep_kernel(const int* __restrict__ eidx, const int* __restrict__ pairs,
                            const int* __restrict__ num_obj, const int* __restrict__ num_edges,
                            const float* __restrict__ Wn, const float* __restrict__ Wn2,
                            const float* __restrict__ We, const float* __restrict__ We2,
                            const float* __restrict__ lrW1, const float* __restrict__ scrW1,
                            const float* __restrict__ mrW1,
                            const float* __restrict__ lrb1, const float* __restrict__ scrb1,
                            const float* __restrict__ mrb1,
                            const float* __restrict__ lrW2, const float* __restrict__ scrW2,
                            const float* __restrict__ mrW2,
                            const float* __restrict__ lrb2, const float* __restrict__ scrb2,
                            const float* __restrict__ mrb2,
                            long long* __restrict__ offs,
                            __half* __restrict__ WNT, __half* __restrict__ WET,
                            __half* __restrict__ WE2T, __half* __restrict__ W1T,
                            __half* __restrict__ W2T, float* __restrict__ b1c,
                            float* __restrict__ b2c, float* __restrict__ agg)
{
    int t = blockIdx.x * blockDim.x + threadIdx.x;
    if (t >= PRE_TOT) return;
    if (t < PRE_OFFE) {
        int b = t >> 7, r = t & 127;
        offs[LLO_N + t] = (r < num_obj[b]) ? (long long)t * DNd : -1LL;
    } else if (t < PRE_OFFP) {
        int j = t - PRE_OFFE;
        int b = j >> 10, m = j & 1023;
        long long v = -1LL;
        if (m < num_edges[b]) {
            int s = eidx[b * 2 * Mm + m];
            int d = eidx[b * 2 * Mm + Mm + m];
            v = (((long long)b * Nn + s) * Nn + d) * DEe;
        }
        offs[LLO_E + j] = v;
    } else if (t < PRE_WNT) {
        int j = t - PRE_OFFP;
        int b = j >> 9;
        int n0 = pairs[(long long)j * 2 + 0];
        int n1 = pairs[(long long)j * 2 + 1];
        offs[LLO_P + j] = (((long long)b * Nn + n0) * Nn + n1) * DEe;
    } else if (t < PRE_WET) {                        // [Wn|Wn2]^T half [256][512]
        int j = t - PRE_WNT;
        int c = j >> 9, k = j & 511;
        float v = (c < 128) ? Wn[k * 128 + c] : Wn2[k * 128 + (c - 128)];
        WNT[j] = __float2half(v);
    } else if (t < PRE_WE2T) {                       // We^T half [128][256]
        int j = t - PRE_WET;
        int c = j >> 8, k = j & 255;
        WET[j] = __float2half(We[k * 128 + c]);
    } else if (t < PRE_W1T) {                        // We2^T half [128][256]
        int j = t - PRE_WE2T;
        int c = j >> 8, k = j & 255;
        WE2T[j] = __float2half(We2[k * 128 + c]);
    } else if (t < PRE_W2T) {                        // [lr|scr|mr]W1^T half [768][512]
        int j = t - PRE_W1T;
        int c = j >> 9, k = j & 511;
        float v;
        if (c < 256) v = lrW1[k * 256 + c];
        else if (c < 512) v = scrW1[k * 256 + (c - 256)];
        else v = mrW1[k * 256 + (c - 512)];
        W1T[j] = __float2half(v);
    } else if (t < PRE_B1) {                         // block-diag W2^T half [32][768]
        int j = t - PRE_W2T;
        int c = j / 768, k = j % 768;
        float v = 0.f;
        if (c < 9)       { if (k < 256)             v = lrW2[k * 9 + c]; }
        else if (c < 15) { if (k >= 256 && k < 512) v = scrW2[(k - 256) * 6 + (c - 9)]; }
        else             { if (k >= 512)            v = mrW2[(k - 512) * 17 + (c - 15)]; }
        W2T[j] = __float2half(v);
    } else if (t < PRE_B2) {
        int j = t - PRE_B1;
        b1c[j] = (j < 256) ? lrb1[j] : (j < 512 ? scrb1[j - 256] : mrb1[j - 512]);
    } else if (t < PRE_AGG) {
        int j = t - PRE_B2;
        b2c[j] = (j < 9) ? lrb2[j] : (j < 15 ? scrb2[j - 9] : mrb2[j - 15]);
    } else {
        agg[t - PRE_AGG] = 0.f;
    }
}

// ---------------- merged sparse propagation (node + line graph) ----------------
__global__ void prop_all_kernel(const float* __restrict__ adj, const float* __restrict__ t1xp,
                                float* __restrict__ H, const int* __restrict__ num_obj,
                                const float* __restrict__ ladj, const float* __restrict__ T2,
                                const int* __restrict__ eidx, const int* __restrict__ num_edges,
                                float* __restrict__ agg)
{
    __shared__ int s_idx[1024];
    __shared__ float s_val[1024];
    __shared__ int s_cnt;
    const int t = threadIdx.x;

    if (blockIdx.x < 2048) {
        // node graph: h = rowmask(relu((adj+I)@T1))
        int b = blockIdx.x >> 7;
        int r = blockIdx.x & 127;
        int lim = num_obj[b];
        float* orow = H + ((long long)b * 128 + r) * 128;
        if (r >= lim) { orow[t] = 0.f; return; }
        if (t == 0) s_cnt = 0;
        __syncthreads();
        float a = adj[(((long long)b * 128) + r) * 128 + t];
        if (a != 0.f) {
            int p = atomicAdd(&s_cnt, 1);
            s_idx[p] = t; s_val[p] = a;
        }
        __syncthreads();
        const float* Tb = t1xp + (long long)b * 128 * 256;
        float acc = Tb[r * 256 + t];
        int n = s_cnt;
        for (int i = 0; i < n; i++)
            acc = fmaf(s_val[i], Tb[s_idx[i] * 256 + t], acc);
        orow[t] = fmaxf(acc, 0.f);
    } else {
        // line graph: relu((ladj+I)@T2) fused scatter to agg
        int j = blockIdx.x - 2048;
        int b = j >> 10;
        int m = j & 1023;
        if (m >= num_edges[b]) return;
        if (t == 0) s_cnt = 0;
        __syncthreads();
        const float4* lrow4 = (const float4*)(ladj + (((long long)b * 1024) + m) * 1024);
#pragma unroll
        for (int jj = 0; jj < 2; jj++) {
            int base = (t * 2 + jj) * 4;
            float4 v = lrow4[t * 2 + jj];
            float vv[4] = {v.x, v.y, v.z, v.w};
#pragma unroll
            for (int e = 0; e < 4; e++) {
                if (vv[e] != 0.f) {
                    int p = atomicAdd(&s_cnt, 1);
                    s_idx[p] = base + e; s_val[p] = vv[e];
                }
            }
        }
        __syncthreads();
        const float* Tb = T2 + (long long)b * 1024 * 128;
        float acc = Tb[m * 128 + t];
        int n = s_cnt;
        for (int i = 0; i < n; i++)
            acc = fmaf(s_val[i], Tb[s_idx[i] * 128 + t], acc);
        acc = fmaxf(acc, 0.f);
        int s = eidx[b * 2 * Mm + m];
        atomicAdd(&agg[((long long)b * 128 + s) * 128 + t], acc);
    }
}

// ---------------- classifier input assembly (half output) ----------------
__global__ void ci_assemble_kernel(const float* __restrict__ h, const float* __restrict__ agg,
                                   const float* __restrict__ t1xp, const __half* __restrict__ qp,
                                   const int* __restrict__ pairs, const int* __restrict__ num_obj,
                                   __half* __restrict__ ci)
{
    int bp = blockIdx.x;
    int b = bp >> 9;
    int t = threadIdx.x;
    int n0 = pairs[(long long)bp * 2 + 0];
    int n1 = pairs[(long long)bp * 2 + 1];
    int no = num_obj[b];

    const float* hb = h + (long long)b * 128 * 128;
    const float* ab = agg + (long long)b * 128 * 128;
    const float* xb = t1xp + (long long)b * 128 * 256 + 128;

    float hv = hb[n0 * 128 + t] + hb[n1 * 128 + t];
    float av = (n0 < no ? ab[n0 * 128 + t] : 0.f) + (n1 < no ? ab[n1 * 128 + t] : 0.f);
    float pm = fmaxf(xb[n0 * 256 + t] + xb[n1 * 256 + t], 0.f);
    float qv = __half2float(qp[(long long)bp * 128 + t]);

    __half* o = ci + (long long)bp * 512;
    o[t] = __float2half(hv);
    o[128 + t] = __float2half(av);
    o[256 + t] = __float2half(pm);
    o[384 + t] = __float2half(qv);
}

// ---------------- launch ----------------
extern "C" void kernel_launch(void* const* d_in, const int* in_sizes, int n_in,
                              void* d_out, int out_size)
{
    const float* node_features = (const float*)d_in[0];
    const float* edge_features = (const float*)d_in[1];
    const float* adj           = (const float*)d_in[2];
    const float* ladj          = (const float*)d_in[3];
    const int*   edge_index    = (const int*)d_in[4];
    const int*   pairs         = (const int*)d_in[5];
    const int*   num_obj       = (const int*)d_in[6];
    const int*   num_edges     = (const int*)d_in[7];
    const float* Wn  = (const float*)d_in[8];
    const float* We  = (const float*)d_in[9];
    const float* Wn2 = (const float*)d_in[10];
    const float* We2 = (const float*)d_in[11];
    const float* scr_W1 = (const float*)d_in[12];
    const float* scr_b1 = (const float*)d_in[13];
    const float* scr_W2 = (const float*)d_in[14];
    const float* scr_b2 = (const float*)d_in[15];
    const float* lr_W1 = (const float*)d_in[16];
    const float* lr_b1 = (const float*)d_in[17];
    const float* lr_W2 = (const float*)d_in[18];
    const float* lr_b2 = (const float*)d_in[19];
    const float* mr_W1 = (const float*)d_in[20];
    const float* mr_b1 = (const float*)d_in[21];
    const float* mr_W2 = (const float*)d_in[22];
    const float* mr_b2 = (const float*)d_in[23];

    float* out = (float*)d_out;

    float* sc = nullptr;
    cudaGetSymbolAddress((void**)&sc, g_scratch);

    long long* OFFS = (long long*)(sc + OFF_OFFS);
    float*  T1XP = sc + OFF_T1XP;
    float*  T2   = sc + OFF_T2;
    float*  H    = sc + OFF_H;
    float*  AGG  = sc + OFF_AGG;
    __half* QPh  = (__half*)(sc + OFF_QP);
    __half* CIh  = (__half*)(sc + OFF_CI);
    __half* HIDh = (__half*)(sc + OFF_HID);
    __half* WNT  = (__half*)(sc + OFF_WNT);
    __half* WET  = (__half*)(sc + OFF_WET);
    __half* WE2T = (__half*)(sc + OFF_WE2T);
    __half* W1T  = (__half*)(sc + OFF_W1T);
    __half* W2T  = (__half*)(sc + OFF_W2T);
    float*  B1C  = sc + OFF_B1C;
    float*  B2C  = sc + OFF_B2C;

    // 1. prep
    prep_kernel<<<(PRE_TOT + 255) / 256, 256>>>(
        edge_index, pairs, num_obj, num_edges,
        Wn, Wn2, We, We2, lr_W1, scr_W1, mr_W1, lr_b1, scr_b1, mr_b1,
        lr_W2, scr_W2, mr_W2, lr_b2, scr_b2, mr_b2,
        OFFS, WNT, WET, WE2T, W1T, W2T, B1C, B2C, AGG);

    // 2. segmented GEMM: T1XP + T2 + QP in one wave
    gemm_seg_kernel<<<448, 256>>>(
        node_features, edge_features, WNT, WET, WE2T, OFFS, T1XP, T2, QPh);

    // 3. merged sparse propagation (node + line graph w/ fused scatter)
    prop_all_kernel<<<2048 + Bb * Mm, 128>>>(
        adj, T1XP, H, num_obj, ladj, T2, edge_index, num_edges, AGG);

    // 4. ci assembly (8192 x 512, half)
    ci_assemble_kernel<<<Bb * Pp, 128>>>(H, AGG, T1XP, QPh, pairs, num_obj, CIh);

    // 5. fused head layer-1 (8192 x 768 x 512)
    gemm_hid_kernel<<<dim3(6, 64), 256>>>(CIh, W1T, B1C, HIDh);

    // 6. layer-2 GEMM (8192 x 32 x 768, block-diag) with scatter epilogue
    gemm_l2_kernel<<<128, 128>>>(HIDh, W2T, B2C, out);
}